// round 2
// baseline (speedup 1.0000x reference)
#include <cuda_runtime.h>

// Problem constants
#define B_   8
#define C_   256
#define N_   4096
#define CQ_  32

// ---------------------------------------------------------------------------
// Scratch (device globals: allocation-free per harness rules)
// q, k stored [b][32][N]; v stored [b][256][N]  (all K-major along N)
// ---------------------------------------------------------------------------
__device__ float g_q[B_ * CQ_ * N_];
__device__ float g_k[B_ * CQ_ * N_];
__device__ float g_v[B_ * C_  * N_];

// ---------------------------------------------------------------------------
// Projection kernel for q and k (M = 32 each). Block tile: 32 x 128, K=256.
// grid = (N/128, 2(q|k), B), 256 threads. Thread tile 2(o) x 8(n).
// ---------------------------------------------------------------------------
__global__ __launch_bounds__(256, 2)
void proj_qk_kernel(const float* __restrict__ x,
                    const float* __restrict__ wq, const float* __restrict__ bq,
                    const float* __restrict__ wk, const float* __restrict__ bk)
{
    const int b     = blockIdx.z;
    const int which = blockIdx.y;           // 0 -> q, 1 -> k
    const int n0    = blockIdx.x * 128;

    const float* W    = which ? wk : wq;
    const float* bias = which ? bk : bq;
    float*       out  = which ? g_k : g_q;

    __shared__ float Wt[16][36];     // [k][o], transposed W chunk
    __shared__ float Xs[16][132];    // [k][n]

    const int tid = threadIdx.x;
    const int to  = tid >> 4;        // 16 o-groups -> o = to*2
    const int tn  = tid & 15;        // 16 n-groups -> n = tn*8

    float acc[2][8];
#pragma unroll
    for (int r = 0; r < 2; r++)
#pragma unroll
        for (int c = 0; c < 8; c++) acc[r][c] = 0.f;

    for (int kk = 0; kk < 256; kk += 16) {
        // W chunk: 32 o x 16 k = 512 elems -> 2/thread
        {
            int e = tid * 2;
            int o = e >> 4;
            int k = e & 15;
            float2 wv2 = *(const float2*)&W[o * 256 + kk + k];
            Wt[k][o]     = wv2.x;
            Wt[k + 1][o] = wv2.y;
        }
        // X chunk: 16 k x 128 n -> 8/thread (2 float4), coalesced
        {
            int k = tid >> 4;
            int n = (tid & 15) * 8;
            const float* xp = &x[((size_t)b * C_ + (kk + k)) * N_ + n0 + n];
            *(float4*)&Xs[k][n]     = *(const float4*)xp;
            *(float4*)&Xs[k][n + 4] = *(const float4*)(xp + 4);
        }
        __syncthreads();
#pragma unroll
        for (int k = 0; k < 16; k++) {
            float a0 = Wt[k][to * 2 + 0];
            float a1 = Wt[k][to * 2 + 1];
            float4 b0 = *(float4*)&Xs[k][tn * 8];
            float4 b1 = *(float4*)&Xs[k][tn * 8 + 4];
            float rb[8] = {b0.x, b0.y, b0.z, b0.w, b1.x, b1.y, b1.z, b1.w};
#pragma unroll
            for (int c = 0; c < 8; c++) {
                acc[0][c] += a0 * rb[c];
                acc[1][c] += a1 * rb[c];
            }
        }
        __syncthreads();
    }
#pragma unroll
    for (int r = 0; r < 2; r++) {
        int o = to * 2 + r;
        float bv_ = bias[o];
        float* op = &out[((size_t)b * CQ_ + o) * N_ + n0 + tn * 8];
        float4 o0 = {acc[r][0] + bv_, acc[r][1] + bv_, acc[r][2] + bv_, acc[r][3] + bv_};
        float4 o1 = {acc[r][4] + bv_, acc[r][5] + bv_, acc[r][6] + bv_, acc[r][7] + bv_};
        *(float4*)op       = o0;
        *(float4*)(op + 4) = o1;
    }
}

// ---------------------------------------------------------------------------
// Projection kernel for v (M = 256). Block tile 128 x 128, K=256.
// grid = (N/128, 2, B), 256 threads. Thread tile 8 x 8.
// ---------------------------------------------------------------------------
__global__ __launch_bounds__(256, 2)
void proj_v_kernel(const float* __restrict__ x,
                   const float* __restrict__ wv, const float* __restrict__ bv)
{
    const int b  = blockIdx.z;
    const int o0g = blockIdx.y * 128;
    const int n0 = blockIdx.x * 128;

    __shared__ float Wt[16][132];    // [k][o]
    __shared__ float Xs[16][132];    // [k][n]

    const int tid = threadIdx.x;
    const int to  = tid >> 4;        // o = to*8
    const int tn  = tid & 15;        // n = tn*8

    float acc[8][8];
#pragma unroll
    for (int r = 0; r < 8; r++)
#pragma unroll
        for (int c = 0; c < 8; c++) acc[r][c] = 0.f;

    for (int kk = 0; kk < 256; kk += 16) {
        // W chunk: 128 o x 16 k = 2048 elems -> 8/thread
        {
            int o = tid >> 1;                 // 0..127
            int k = (tid & 1) * 8;            // 0 or 8
            const float* wp = &wv[(size_t)(o0g + o) * 256 + kk + k];
            float4 w0 = *(const float4*)wp;
            float4 w1 = *(const float4*)(wp + 4);
            Wt[k + 0][o] = w0.x; Wt[k + 1][o] = w0.y;
            Wt[k + 2][o] = w0.z; Wt[k + 3][o] = w0.w;
            Wt[k + 4][o] = w1.x; Wt[k + 5][o] = w1.y;
            Wt[k + 6][o] = w1.z; Wt[k + 7][o] = w1.w;
        }
        // X chunk: 16 k x 128 n -> 8/thread
        {
            int k = tid >> 4;
            int n = (tid & 15) * 8;
            const float* xp = &x[((size_t)b * C_ + (kk + k)) * N_ + n0 + n];
            *(float4*)&Xs[k][n]     = *(const float4*)xp;
            *(float4*)&Xs[k][n + 4] = *(const float4*)(xp + 4);
        }
        __syncthreads();
#pragma unroll
        for (int k = 0; k < 16; k++) {
            float4 a0 = *(float4*)&Wt[k][to * 8];
            float4 a1 = *(float4*)&Wt[k][to * 8 + 4];
            float4 b0 = *(float4*)&Xs[k][tn * 8];
            float4 b1 = *(float4*)&Xs[k][tn * 8 + 4];
            float ra[8] = {a0.x, a0.y, a0.z, a0.w, a1.x, a1.y, a1.z, a1.w};
            float rb[8] = {b0.x, b0.y, b0.z, b0.w, b1.x, b1.y, b1.z, b1.w};
#pragma unroll
            for (int r = 0; r < 8; r++)
#pragma unroll
                for (int c = 0; c < 8; c++) acc[r][c] += ra[r] * rb[c];
        }
        __syncthreads();
    }
#pragma unroll
    for (int r = 0; r < 8; r++) {
        int o = o0g + to * 8 + r;
        float bb = bv[o];
        float* op = &g_v[((size_t)b * C_ + o) * N_ + n0 + tn * 8];
        float4 o0 = {acc[r][0] + bb, acc[r][1] + bb, acc[r][2] + bb, acc[r][3] + bb};
        float4 o1 = {acc[r][4] + bb, acc[r][5] + bb, acc[r][6] + bb, acc[r][7] + bb};
        *(float4*)op       = o0;
        *(float4*)(op + 4) = o1;
    }
}

// ---------------------------------------------------------------------------
// Fused flash attention + epilogue.
// grid = (N/64, B), 256 threads, 2 blocks/SM.
// Per block: 64 query rows (i), stream 64-key tiles (j), online softmax,
// acc[64 x 256] fp32 in registers (8x8 per thread), epilogue y = g*out + x.
// ---------------------------------------------------------------------------
#define QS_STRIDE 33
#define SS_STRIDE 65
#define VT_STRIDE 260
#define O2_STRIDE 257

#define QS_OFF 0
#define KS_OFF (QS_OFF + 64 * QS_STRIDE)
#define SS_OFF (KS_OFF + 64 * QS_STRIDE)
#define VT_OFF (SS_OFF + 64 * SS_STRIDE)
#define M_OFF  (VT_OFF + 64 * VT_STRIDE)
#define L_OFF  (M_OFF + 64)
#define CS_OFF (L_OFF + 64)
#define SMEM_FLOATS (CS_OFF + 64)
#define SMEM_BYTES  (SMEM_FLOATS * 4)

__global__ __launch_bounds__(256, 2)
void attn_kernel(const float* __restrict__ x,
                 const float* __restrict__ gamma,
                 float* __restrict__ y)
{
    extern __shared__ float sm[];
    float* qs = sm + QS_OFF;   // [i][33]  (i-major, o fast)
    float* ks = sm + KS_OFF;   // [j][33]
    float* Ss = sm + SS_OFF;   // [i][65]  scores -> probabilities
    float* vt = sm + VT_OFF;   // [j][260] transposed v tile; reused as outs2
    float* m_ = sm + M_OFF;
    float* l_ = sm + L_OFF;
    float* cs = sm + CS_OFF;

    const int b   = blockIdx.y;
    const int i0g = blockIdx.x * 64;
    const int tid = threadIdx.x;

    // --- load q tile: q[b][o][i0g + i] -> qs[i][o]  (32 x 64, transposed) ---
    {
        int e  = tid * 2;
        int o  = e >> 4;            // 0..31
        int i4 = e & 15;            // even float4 index along i
        const float* qp = &g_q[((size_t)b * CQ_ + o) * N_ + i0g + i4 * 4];
        float4 a = *(const float4*)qp;
        float4 c = *(const float4*)(qp + 4);
        qs[(i4 * 4 + 0) * QS_STRIDE + o] = a.x;
        qs[(i4 * 4 + 1) * QS_STRIDE + o] = a.y;
        qs[(i4 * 4 + 2) * QS_STRIDE + o] = a.z;
        qs[(i4 * 4 + 3) * QS_STRIDE + o] = a.w;
        qs[(i4 * 4 + 4) * QS_STRIDE + o] = c.x;
        qs[(i4 * 4 + 5) * QS_STRIDE + o] = c.y;
        qs[(i4 * 4 + 6) * QS_STRIDE + o] = c.z;
        qs[(i4 * 4 + 7) * QS_STRIDE + o] = c.w;
    }
    if (tid < 64) { m_[tid] = -1e30f; l_[tid] = 0.f; }

    float acc[8][8];
#pragma unroll
    for (int r = 0; r < 8; r++)
#pragma unroll
        for (int c = 0; c < 8; c++) acc[r][c] = 0.f;

    const int ti  = tid >> 5;       // 8 groups -> i0 = ti*8
    const int tc  = tid & 31;       // 32 groups -> c0 = tc*8
    const int ii0 = ti * 8;
    const int c0  = tc * 8;

    for (int jt = 0; jt < 64; jt++) {
        const int j0g = jt * 64;
        __syncthreads();   // previous AV reads of vt/Ss complete before reload

        // --- load k tile: k[b][o][j0g + j] -> ks[j][o] ---
        {
            int e  = tid * 2;
            int o  = e >> 4;
            int j4 = e & 15;
            const float* kp = &g_k[((size_t)b * CQ_ + o) * N_ + j0g + j4 * 4];
            float4 a = *(const float4*)kp;
            float4 c = *(const float4*)(kp + 4);
            ks[(j4 * 4 + 0) * QS_STRIDE + o] = a.x;
            ks[(j4 * 4 + 1) * QS_STRIDE + o] = a.y;
            ks[(j4 * 4 + 2) * QS_STRIDE + o] = a.z;
            ks[(j4 * 4 + 3) * QS_STRIDE + o] = a.w;
            ks[(j4 * 4 + 4) * QS_STRIDE + o] = c.x;
            ks[(j4 * 4 + 5) * QS_STRIDE + o] = c.y;
            ks[(j4 * 4 + 6) * QS_STRIDE + o] = c.z;
            ks[(j4 * 4 + 7) * QS_STRIDE + o] = c.w;
        }
        // --- load v tile: v[b][c][j0g + j] -> vt[j][c]  (256 x 64, transposed) ---
        {
            int j4 = tid & 15;
            int cb = tid >> 4;
#pragma unroll
            for (int r = 0; r < 16; r++) {
                int c = r * 16 + cb;
                float4 a = *(const float4*)&g_v[((size_t)b * C_ + c) * N_ + j0g + j4 * 4];
                vt[(j4 * 4 + 0) * VT_STRIDE + c] = a.x;
                vt[(j4 * 4 + 1) * VT_STRIDE + c] = a.y;
                vt[(j4 * 4 + 2) * VT_STRIDE + c] = a.z;
                vt[(j4 * 4 + 3) * VT_STRIDE + c] = a.w;
            }
        }
        __syncthreads();

        // --- S = q_tile (64x32) @ k_tile^T (32x64) -> Ss[i][j] ---
        {
            const int sj0 = (tid & 31) * 2;     // 2 j per thread
            const int si0 = (tid >> 5) * 8;     // 8 i per thread
            float s[8][2];
#pragma unroll
            for (int r = 0; r < 8; r++) { s[r][0] = 0.f; s[r][1] = 0.f; }
#pragma unroll
            for (int o = 0; o < 32; o++) {
                float k0 = ks[(sj0 + 0) * QS_STRIDE + o];
                float k1 = ks[(sj0 + 1) * QS_STRIDE + o];
#pragma unroll
                for (int r = 0; r < 8; r++) {
                    float qv = qs[(si0 + r) * QS_STRIDE + o];
                    s[r][0] += qv * k0;
                    s[r][1] += qv * k1;
                }
            }
#pragma unroll
            for (int r = 0; r < 8; r++) {
                Ss[(si0 + r) * SS_STRIDE + sj0 + 0] = s[r][0];
                Ss[(si0 + r) * SS_STRIDE + sj0 + 1] = s[r][1];
            }
        }
        __syncthreads();

        // --- online softmax: 4 lanes per row ---
        {
            const int i  = tid >> 2;
            const int qq = tid & 3;
            float* srow = &Ss[i * SS_STRIDE + qq * 16];
            float mx = -1e30f;
#pragma unroll
            for (int jj = 0; jj < 16; jj++) mx = fmaxf(mx, srow[jj]);
            mx = fmaxf(mx, __shfl_xor_sync(0xffffffffu, mx, 1));
            mx = fmaxf(mx, __shfl_xor_sync(0xffffffffu, mx, 2));
            float mo = m_[i];
            float mn = fmaxf(mo, mx);
            float cf = __expf(mo - mn);
            float sum = 0.f;
#pragma unroll
            for (int jj = 0; jj < 16; jj++) {
                float p = __expf(srow[jj] - mn);
                srow[jj] = p;
                sum += p;
            }
            sum += __shfl_xor_sync(0xffffffffu, sum, 1);
            sum += __shfl_xor_sync(0xffffffffu, sum, 2);
            if (qq == 0) {
                m_[i] = mn;
                cs[i] = cf;
                l_[i] = l_[i] * cf + sum;
            }
        }
        __syncthreads();

        // --- AV: acc[i][c] = acc*cf + P(64x64) @ vt(64x256) ---
        {
#pragma unroll
            for (int r = 0; r < 8; r++) {
                float f = cs[ii0 + r];
#pragma unroll
                for (int c = 0; c < 8; c++) acc[r][c] *= f;
            }
#pragma unroll 2
            for (int j = 0; j < 64; j++) {
                float4 v0 = *(float4*)&vt[j * VT_STRIDE + c0];
                float4 v1 = *(float4*)&vt[j * VT_STRIDE + c0 + 4];
                float vv[8] = {v0.x, v0.y, v0.z, v0.w, v1.x, v1.y, v1.z, v1.w};
                float p[8];
#pragma unroll
                for (int r = 0; r < 8; r++) p[r] = Ss[(ii0 + r) * SS_STRIDE + j];
#pragma unroll
                for (int r = 0; r < 8; r++)
#pragma unroll
                    for (int c = 0; c < 8; c++) acc[r][c] += p[r] * vv[c];
            }
        }
    }
    __syncthreads();

    // --- normalize + stage transposed: outs2[i][c] (reuse vt) ---
    float* outs2 = vt;
#pragma unroll
    for (int r = 0; r < 8; r++) {
        float inv = 1.0f / l_[ii0 + r];
#pragma unroll
        for (int c = 0; c < 8; c++)
            outs2[(ii0 + r) * O2_STRIDE + c0 + c] = acc[r][c] * inv;
    }
    __syncthreads();

    // --- epilogue: y[b][c][i] = gamma*out + x, coalesced along i ---
    {
        const float g   = gamma[0];
        const int w     = tid >> 5;
        const int lane  = tid & 31;
        for (int cl = w; cl < 256; cl += 8) {
            float o0 = outs2[(2 * lane + 0) * O2_STRIDE + cl];
            float o1 = outs2[(2 * lane + 1) * O2_STRIDE + cl];
            size_t gb = ((size_t)b * C_ + cl) * N_ + i0g + 2 * lane;
            float2 xv = *(const float2*)&x[gb];
            float2 yv = {g * o0 + xv.x, g * o1 + xv.y};
            *(float2*)&y[gb] = yv;
        }
    }
}

// ---------------------------------------------------------------------------
extern "C" void kernel_launch(void* const* d_in, const int* in_sizes, int n_in,
                              void* d_out, int out_size)
{
    const float* x     = (const float*)d_in[0];
    const float* wq    = (const float*)d_in[1];
    const float* bq    = (const float*)d_in[2];
    const float* wk    = (const float*)d_in[3];
    const float* bk    = (const float*)d_in[4];
    const float* wv    = (const float*)d_in[5];
    const float* bv    = (const float*)d_in[6];
    const float* gamma = (const float*)d_in[7];
    float* y = (float*)d_out;

    cudaFuncSetAttribute(attn_kernel,
                         cudaFuncAttributeMaxDynamicSharedMemorySize, SMEM_BYTES);

    proj_qk_kernel<<<dim3(N_ / 128, 2, B_), 256>>>(x, wq, bq, wk, bk);
    proj_v_kernel <<<dim3(N_ / 128, 2, B_), 256>>>(x, wv, bv);
    attn_kernel   <<<dim3(N_ / 64, B_), 256, SMEM_BYTES>>>(x, gamma, y);
}

// round 4
// speedup vs baseline: 5.5014x; 5.5014x over previous
#include <cuda_runtime.h>
#include <cuda_bf16.h>
#include <stdint.h>

#define B_   8
#define C_   256
#define N_   4096
#define CQ_  32

// ---------------------------------------------------------------------------
// PTX helpers (sm_80/sm_90-class only -- NO tcgen05)
// ---------------------------------------------------------------------------
__device__ __forceinline__ uint32_t smem_u32(const void* p) {
    uint32_t a;
    asm("{ .reg .u64 t; cvta.to.shared.u64 t, %1; cvt.u32.u64 %0, t; }"
        : "=r"(a) : "l"(p));
    return a;
}

#define MBARRIER_INIT(mbar, count) \
    asm volatile("mbarrier.init.shared.b64 [%0], %1;" \
        :: "r"((uint32_t)(mbar)), "r"((uint32_t)(count)) : "memory")
#define MBARRIER_EXPECT_TX(mbar, bytes) \
    asm volatile("mbarrier.arrive.expect_tx.shared.b64 _, [%0], %1;" \
        :: "r"((uint32_t)(mbar)), "r"((uint32_t)(bytes)) : "memory")

#define MBARRIER_WAIT_PARITY(mbar, parity) do {                                   \
    uint32_t _m = (uint32_t)(mbar); uint32_t _p = (uint32_t)(parity);             \
    uint32_t _done;                                                               \
    asm volatile("{\n\t.reg .pred p;\n\t"                                         \
        "mbarrier.try_wait.parity.acquire.cta.shared::cta.b64 p, [%1], %2;\n\t"   \
        "selp.b32 %0, 1, 0, p;\n\t}"                                              \
        : "=r"(_done) : "r"(_m), "r"(_p) : "memory");                             \
    if (!_done) {                                                                 \
        asm volatile("{\n\t.reg .pred P1;\n\t"                                    \
            "WAIT_LOOP_%=:\n\t"                                                   \
            "mbarrier.try_wait.parity.acquire.cta.shared::cta.b64 P1, [%0], %1, 0x989680;\n\t" \
            "@P1 bra.uni WAIT_DONE_%=;\n\t"                                       \
            "bra.uni WAIT_LOOP_%=;\n\t"                                           \
            "WAIT_DONE_%=:\n\t}"                                                  \
            :: "r"(_m), "r"(_p) : "memory");                                      \
    }                                                                             \
} while (0)

#define BULK_G2S(dst, src, bytes, mbar) \
    asm volatile("cp.async.bulk.shared::cluster.global.mbarrier::complete_tx::bytes " \
        "[%0], [%1], %2, [%3];" \
        :: "r"((uint32_t)(dst)), "l"(__cvta_generic_to_global(src)), \
           "r"((uint32_t)(bytes)), "r"((uint32_t)(mbar)) : "memory")

__device__ __forceinline__ void ldsm4(uint32_t r[4], uint32_t addr) {
    asm volatile("ldmatrix.sync.aligned.m8n8.x4.shared.b16 {%0,%1,%2,%3}, [%4];"
        : "=r"(r[0]), "=r"(r[1]), "=r"(r[2]), "=r"(r[3]) : "r"(addr));
}

__device__ __forceinline__ void mma16816(float d[4], const uint32_t a[4],
                                         uint32_t b0, uint32_t b1) {
    asm volatile("mma.sync.aligned.m16n8k16.row.col.f32.bf16.bf16.f32 "
        "{%0,%1,%2,%3}, {%4,%5,%6,%7}, {%8,%9}, {%0,%1,%2,%3};"
        : "+f"(d[0]), "+f"(d[1]), "+f"(d[2]), "+f"(d[3])
        : "r"(a[0]), "r"(a[1]), "r"(a[2]), "r"(a[3]), "r"(b0), "r"(b1));
}

__device__ __forceinline__ uint32_t pack_bf16x2(float hi, float lo) {
    uint32_t r;
    asm("cvt.rn.satfinite.bf16x2.f32 %0, %1, %2;" : "=r"(r) : "f"(hi), "f"(lo));
    return r;
}

// ---------------------------------------------------------------------------
// Gmem scratch: bf16 tiles, XOR-swizzled 16B groups (g ^= row&7)
// g_qh[b][qt64][64 rows][64 bf16: hi(0..31)|lo(32..63)]   8KB/tile
// g_kh[b][kt32][128 rows][64 bf16: hi|lo]                 16KB/tile
// g_vh[b][kt32][256 ch][128 keys bf16]                    64KB/tile
// ---------------------------------------------------------------------------
__device__ __align__(16) unsigned char g_qh[(size_t)B_ * 64 * 8192];
__device__ __align__(16) unsigned char g_kh[(size_t)B_ * 32 * 16384];
__device__ __align__(16) unsigned char g_vh[(size_t)B_ * 32 * 65536];

// ---------------------------------------------------------------------------
// proj_qk: q/k = W(32x256) @ x + b -> hi/lo bf16 swizzled tiles
// grid (32, 2, 8), 256 threads
// ---------------------------------------------------------------------------
__global__ __launch_bounds__(256, 2)
void proj_qk_kernel(const float* __restrict__ x,
                    const float* __restrict__ wq, const float* __restrict__ bq,
                    const float* __restrict__ wk, const float* __restrict__ bk)
{
    const int b     = blockIdx.z;
    const int which = blockIdx.y;
    const int n0    = blockIdx.x * 128;

    const float* W    = which ? wk : wq;
    const float* bias = which ? bk : bq;

    __shared__ float Wt[16][36];
    __shared__ float Xs[16][132];
    __shared__ float Sg[32][133];

    const int tid = threadIdx.x;
    const int to  = tid >> 4;
    const int tn  = tid & 15;

    float acc[2][8];
#pragma unroll
    for (int r = 0; r < 2; r++)
#pragma unroll
        for (int c = 0; c < 8; c++) acc[r][c] = 0.f;

    for (int kk = 0; kk < 256; kk += 16) {
        {
            int e = tid * 2;
            int o = e >> 4;
            int k = e & 15;
            float2 wv2 = *(const float2*)&W[o * 256 + kk + k];
            Wt[k][o] = wv2.x;
            Wt[k + 1][o] = wv2.y;
        }
        {
            int k = tid >> 4;
            int n = (tid & 15) * 8;
            const float* xp = &x[((size_t)b * C_ + (kk + k)) * N_ + n0 + n];
            *(float4*)&Xs[k][n]     = *(const float4*)xp;
            *(float4*)&Xs[k][n + 4] = *(const float4*)(xp + 4);
        }
        __syncthreads();
#pragma unroll
        for (int k = 0; k < 16; k++) {
            float a0 = Wt[k][to * 2 + 0];
            float a1 = Wt[k][to * 2 + 1];
            float4 b0 = *(float4*)&Xs[k][tn * 8];
            float4 b1 = *(float4*)&Xs[k][tn * 8 + 4];
            float rb[8] = {b0.x, b0.y, b0.z, b0.w, b1.x, b1.y, b1.z, b1.w};
#pragma unroll
            for (int c = 0; c < 8; c++) {
                acc[0][c] += a0 * rb[c];
                acc[1][c] += a1 * rb[c];
            }
        }
        __syncthreads();
    }
#pragma unroll
    for (int r = 0; r < 2; r++) {
        float bv_ = bias[to * 2 + r];
#pragma unroll
        for (int c = 0; c < 8; c++) Sg[to * 2 + r][tn * 8 + c] = acc[r][c] + bv_;
    }
    __syncthreads();

    // write 1024 x 16B swizzled chunks: row nl (0..127), group g (0..7)
#pragma unroll
    for (int cc = 0; cc < 4; cc++) {
        int m  = tid + 256 * cc;
        int nl = m >> 3;
        int g  = m & 7;
        int o0 = (g & 3) * 8;
        bool is_lo = g >= 4;
        union { uint4 u; __nv_bfloat16 h[8]; } pk;
#pragma unroll
        for (int j = 0; j < 8; j++) {
            float v = Sg[o0 + j][nl];
            __nv_bfloat16 hi = __float2bfloat16(v);
            pk.h[j] = is_lo ? __float2bfloat16(v - __bfloat162float(hi)) : hi;
        }
        unsigned char* dst;
        if (which) {   // k: 128-row tiles
            dst = g_kh + ((size_t)(b * 32 + blockIdx.x)) * 16384
                + nl * 128 + ((g ^ (nl & 7)) << 4);
        } else {       // q: 64-row tiles
            int tile = blockIdx.x * 2 + (nl >> 6);
            dst = g_qh + ((size_t)(b * 64 + tile)) * 8192
                + (nl & 63) * 128 + ((g ^ (nl & 7)) << 4);
        }
        *(uint4*)dst = pk.u;
    }
}

// ---------------------------------------------------------------------------
// proj_v: v = Wv(256x256) @ x + b -> bf16 swizzled [ch][key] tiles
// grid (32, 2, 8), 256 threads, thread tile 8x8
// ---------------------------------------------------------------------------
__global__ __launch_bounds__(256, 2)
void proj_v_kernel(const float* __restrict__ x,
                   const float* __restrict__ wv, const float* __restrict__ bv)
{
    const int b   = blockIdx.z;
    const int o0g = blockIdx.y * 128;

    __shared__ float Wt[16][132];
    __shared__ float Xs[16][132];

    const int tid = threadIdx.x;
    const int to  = tid >> 4;
    const int tn  = tid & 15;
    const int n0  = blockIdx.x * 128;

    float acc[8][8];
#pragma unroll
    for (int r = 0; r < 8; r++)
#pragma unroll
        for (int c = 0; c < 8; c++) acc[r][c] = 0.f;

    for (int kk = 0; kk < 256; kk += 16) {
        {
            int o = tid >> 1;
            int k = (tid & 1) * 8;
            const float* wp = &wv[(size_t)(o0g + o) * 256 + kk + k];
            float4 w0 = *(const float4*)wp;
            float4 w1 = *(const float4*)(wp + 4);
            Wt[k + 0][o] = w0.x; Wt[k + 1][o] = w0.y;
            Wt[k + 2][o] = w0.z; Wt[k + 3][o] = w0.w;
            Wt[k + 4][o] = w1.x; Wt[k + 5][o] = w1.y;
            Wt[k + 6][o] = w1.z; Wt[k + 7][o] = w1.w;
        }
        {
            int k = tid >> 4;
            int n = (tid & 15) * 8;
            const float* xp = &x[((size_t)b * C_ + (kk + k)) * N_ + n0 + n];
            *(float4*)&Xs[k][n]     = *(const float4*)xp;
            *(float4*)&Xs[k][n + 4] = *(const float4*)(xp + 4);
        }
        __syncthreads();
#pragma unroll
        for (int k = 0; k < 16; k++) {
            float4 a0 = *(float4*)&Wt[k][to * 8];
            float4 a1 = *(float4*)&Wt[k][to * 8 + 4];
            float4 b0 = *(float4*)&Xs[k][tn * 8];
            float4 b1 = *(float4*)&Xs[k][tn * 8 + 4];
            float ra[8] = {a0.x, a0.y, a0.z, a0.w, a1.x, a1.y, a1.z, a1.w};
            float rb[8] = {b0.x, b0.y, b0.z, b0.w, b1.x, b1.y, b1.z, b1.w};
#pragma unroll
            for (int r = 0; r < 8; r++)
#pragma unroll
                for (int c = 0; c < 8; c++) acc[r][c] += ra[r] * rb[c];
        }
        __syncthreads();
    }

    // store: tile = blockIdx.x (128 keys), row = ch (256B), group gk = tn
    unsigned char* tile = g_vh + ((size_t)(b * 32 + blockIdx.x)) * 65536;
#pragma unroll
    for (int r = 0; r < 8; r++) {
        int ch = o0g + to * 8 + r;
        float bb = bv[ch];
        union { uint4 u; __nv_bfloat16 h[8]; } pk;
#pragma unroll
        for (int c = 0; c < 8; c++) pk.h[c] = __float2bfloat16(acc[r][c] + bb);
        *(uint4*)(tile + ch * 256 + ((tn ^ (ch & 7)) << 4)) = pk.u;
    }
}

// ---------------------------------------------------------------------------
// Attention: mma.sync flash attention, 64 queries/CTA, grid (64, 8), 256 thr
// ---------------------------------------------------------------------------
#define SQ_  0u
#define SK_  8192u
#define SV_  40960u
#define SP_  172032u          // 64 rows * 272 B
#define SL_  189440u          // 64 floats
#define SMB_ 189696u          // 2 mbarriers
#define SMEM_TOTAL 189952

__global__ __launch_bounds__(256, 1)
void attn_kernel(const float* __restrict__ x,
                 const float* __restrict__ gamma,
                 float* __restrict__ y)
{
    extern __shared__ __align__(16) unsigned char smem[];
    const uint32_t sb = smem_u32(smem);
    const int tid  = threadIdx.x;
    const int lane = tid & 31;
    const int w    = tid >> 5;
    const int b    = blockIdx.y;
    const int qt   = blockIdx.x;
    const int ib   = w >> 1;          // i-block (16 rows)
    const int half = w & 1;           // j/c half
    const int gr   = lane >> 2;
    const int tc   = lane & 3;

    if (tid < 64) *(float*)(smem + SL_ + tid * 4) = 0.f;
    if (tid == 0) {
        MBARRIER_INIT(sb + SMB_ + 0, 1);
        MBARRIER_INIT(sb + SMB_ + 8, 1);
    }
    __syncthreads();

    const unsigned char* gq  = g_qh + ((size_t)(b * 64 + qt)) * 8192;
    const unsigned char* gk0 = g_kh + ((size_t)b * 32) * 16384;
    const unsigned char* gv0 = g_vh + ((size_t)b * 32) * 65536;

    // prologue: Q + tile0 into buf0
    if (tid == 0) {
        MBARRIER_EXPECT_TX(sb + SMB_ + 0, 8192 + 16384 + 65536);
        BULK_G2S(sb + SQ_, gq, 8192, sb + SMB_ + 0);
        BULK_G2S(sb + SK_, gk0, 16384, sb + SMB_ + 0);
        BULK_G2S(sb + SV_, gv0, 65536, sb + SMB_ + 0);
    }

    float accs[16][4];
#pragma unroll
    for (int i = 0; i < 16; i++)
#pragma unroll
        for (int j = 0; j < 4; j++) accs[i][j] = 0.f;

    uint32_t Qa[4][4];
    float lsA = 0.f, lsB = 0.f;

    for (int jt = 0; jt < 32; jt++) {
        const int buf = jt & 1;

        // issue next tile copy
        if (tid == 0 && jt < 31) {
            const int nb = (jt + 1) & 1;
            MBARRIER_EXPECT_TX(sb + SMB_ + 8 * nb, 16384 + 65536);
            BULK_G2S(sb + SK_ + nb * 16384, gk0 + (size_t)(jt + 1) * 16384,
                     16384, sb + SMB_ + 8 * nb);
            BULK_G2S(sb + SV_ + nb * 65536, gv0 + (size_t)(jt + 1) * 65536,
                     65536, sb + SMB_ + 8 * nb);
        }

        // wait current tile
        MBARRIER_WAIT_PARITY(sb + SMB_ + 8 * buf, (jt >> 1) & 1);

        if (jt == 0) {
#pragma unroll
            for (int c = 0; c < 4; c++) {
                int row = ib * 16 + (lane & 15);
                int g   = 2 * c + (lane >> 4);
                ldsm4(Qa[c], sb + SQ_ + row * 128 + ((g ^ (row & 7)) << 4));
            }
        }

        // ---- GEMM1 + softmax: S = Q(hi/lo) @ K^T, P = exp(S) ----
        const uint32_t kbase = sb + SK_ + buf * 16384;
#pragma unroll
        for (int nf = 0; nf < 8; nf += 2) {
            uint32_t kb0[8], kb1[8];
            {
                int j0 = half * 64 + nf * 8 + (lane & 7);
                int j1 = j0 + 8;
                int ga = (lane >> 3), gb = 4 + (lane >> 3);
                ldsm4(kb0,     kbase + j0 * 128 + ((ga ^ (j0 & 7)) << 4));
                ldsm4(kb0 + 4, kbase + j0 * 128 + ((gb ^ (j0 & 7)) << 4));
                ldsm4(kb1,     kbase + j1 * 128 + ((ga ^ (j1 & 7)) << 4));
                ldsm4(kb1 + 4, kbase + j1 * 128 + ((gb ^ (j1 & 7)) << 4));
            }
            float d0[4] = {0.f, 0.f, 0.f, 0.f};
            float d1[4] = {0.f, 0.f, 0.f, 0.f};
#pragma unroll
            for (int c = 0; c < 4; c++) {
                mma16816(d0, Qa[c], kb0[2 * c], kb0[2 * c + 1]);
                mma16816(d1, Qa[c], kb1[2 * c], kb1[2 * c + 1]);
                mma16816(d0, Qa[c], kb0[(2 * c + 4) & 7], kb0[(2 * c + 5) & 7]);
                mma16816(d1, Qa[c], kb1[(2 * c + 4) & 7], kb1[(2 * c + 5) & 7]);
            }
#pragma unroll
            for (int q2 = 0; q2 < 2; q2++) {
                float* d = q2 ? d1 : d0;
                float e0 = __expf(d[0]), e1 = __expf(d[1]);
                float e2 = __expf(d[2]), e3 = __expf(d[3]);
                lsA += e0 + e1;
                lsB += e2 + e3;
                int colb = (half * 64 + (nf + q2) * 8 + tc * 2) * 2;
                int r0   = ib * 16 + gr;
                *(uint32_t*)(smem + SP_ + r0 * 272 + colb)       = pack_bf16x2(e1, e0);
                *(uint32_t*)(smem + SP_ + (r0 + 8) * 272 + colb) = pack_bf16x2(e3, e2);
            }
        }
        __syncthreads();

        // ---- GEMM2: O += P @ V ----
        uint32_t Pa[8][4];
#pragma unroll
        for (int kc = 0; kc < 8; kc++) {
            int row = ib * 16 + (lane & 15);
            int cb  = kc * 16 + (lane >> 4) * 8;
            ldsm4(Pa[kc], sb + SP_ + row * 272 + cb * 2);
        }
        const uint32_t vbase = sb + SV_ + buf * 65536;
#pragma unroll
        for (int nf = 0; nf < 16; nf += 2) {
            uint32_t vb0[16], vb1[16];
            {
                int ch0 = half * 128 + nf * 8 + (lane & 7);
                int ch1 = ch0 + 8;
#pragma unroll
                for (int p = 0; p < 4; p++) {
                    int g = 4 * p + (lane >> 3);
                    ldsm4(vb0 + 4 * p, vbase + ch0 * 256 + ((g ^ (ch0 & 7)) << 4));
                    ldsm4(vb1 + 4 * p, vbase + ch1 * 256 + ((g ^ (ch1 & 7)) << 4));
                }
            }
#pragma unroll
            for (int kc = 0; kc < 8; kc++) {
                mma16816(accs[nf],     Pa[kc], vb0[2 * kc], vb0[2 * kc + 1]);
                mma16816(accs[nf + 1], Pa[kc], vb1[2 * kc], vb1[2 * kc + 1]);
            }
        }
        __syncthreads();
    }

    // ---- row-sum reduction ----
    lsA += __shfl_xor_sync(0xffffffffu, lsA, 1);
    lsA += __shfl_xor_sync(0xffffffffu, lsA, 2);
    lsB += __shfl_xor_sync(0xffffffffu, lsB, 1);
    lsB += __shfl_xor_sync(0xffffffffu, lsB, 2);
    if (tc == 0) {
        atomicAdd((float*)(smem + SL_ + (ib * 16 + gr) * 4), lsA);
        atomicAdd((float*)(smem + SL_ + (ib * 16 + gr + 8) * 4), lsB);
    }
    __syncthreads();

    // ---- epilogue: y = gamma * O/l + x ----
    const float gm = gamma[0];
    const int r0   = ib * 16 + gr;
    const float inv0 = 1.0f / *(float*)(smem + SL_ + r0 * 4);
    const float inv8 = 1.0f / *(float*)(smem + SL_ + (r0 + 8) * 4);
    const int i0 = qt * 64;
#pragma unroll
    for (int nf = 0; nf < 16; nf++) {
        int c = half * 128 + nf * 8 + tc * 2;
        size_t base0 = ((size_t)b * C_ + c) * N_ + i0;
        size_t base1 = base0 + N_;
        y[base0 + r0]     = gm * accs[nf][0] * inv0 + x[base0 + r0];
        y[base1 + r0]     = gm * accs[nf][1] * inv0 + x[base1 + r0];
        y[base0 + r0 + 8] = gm * accs[nf][2] * inv8 + x[base0 + r0 + 8];
        y[base1 + r0 + 8] = gm * accs[nf][3] * inv8 + x[base1 + r0 + 8];
    }
}

// ---------------------------------------------------------------------------
extern "C" void kernel_launch(void* const* d_in, const int* in_sizes, int n_in,
                              void* d_out, int out_size)
{
    const float* x     = (const float*)d_in[0];
    const float* wq    = (const float*)d_in[1];
    const float* bq    = (const float*)d_in[2];
    const float* wk    = (const float*)d_in[3];
    const float* bk    = (const float*)d_in[4];
    const float* wv    = (const float*)d_in[5];
    const float* bv    = (const float*)d_in[6];
    const float* gamma = (const float*)d_in[7];
    float* y = (float*)d_out;

    cudaFuncSetAttribute(attn_kernel,
                         cudaFuncAttributeMaxDynamicSharedMemorySize, SMEM_TOTAL);

    proj_qk_kernel<<<dim3(32, 2, B_), 256>>>(x, wq, bq, wk, bk);
    proj_v_kernel <<<dim3(32, 2, B_), 256>>>(x, wv, bv);
    attn_kernel   <<<dim3(64, B_), 256, SMEM_TOTAL>>>(x, gamma, y);
}

// round 5
// speedup vs baseline: 6.9940x; 1.2713x over previous
#include <cuda_runtime.h>
#include <cuda_bf16.h>
#include <stdint.h>

#define B_   8
#define C_   256
#define N_   4096
#define CQ_  32

// ---------------------------------------------------------------------------
// PTX helpers (sm_80/sm_90-class only -- NO tcgen05)
// ---------------------------------------------------------------------------
__device__ __forceinline__ uint32_t smem_u32(const void* p) {
    uint32_t a;
    asm("{ .reg .u64 t; cvta.to.shared.u64 t, %1; cvt.u32.u64 %0, t; }"
        : "=r"(a) : "l"(p));
    return a;
}

#define MBARRIER_INIT(mbar, count) \
    asm volatile("mbarrier.init.shared.b64 [%0], %1;" \
        :: "r"((uint32_t)(mbar)), "r"((uint32_t)(count)) : "memory")
#define MBARRIER_EXPECT_TX(mbar, bytes) \
    asm volatile("mbarrier.arrive.expect_tx.shared.b64 _, [%0], %1;" \
        :: "r"((uint32_t)(mbar)), "r"((uint32_t)(bytes)) : "memory")

#define MBARRIER_WAIT_PARITY(mbar, parity) do {                                   \
    uint32_t _m = (uint32_t)(mbar); uint32_t _p = (uint32_t)(parity);             \
    uint32_t _done;                                                               \
    asm volatile("{\n\t.reg .pred p;\n\t"                                         \
        "mbarrier.try_wait.parity.acquire.cta.shared::cta.b64 p, [%1], %2;\n\t"   \
        "selp.b32 %0, 1, 0, p;\n\t}"                                              \
        : "=r"(_done) : "r"(_m), "r"(_p) : "memory");                             \
    if (!_done) {                                                                 \
        asm volatile("{\n\t.reg .pred P1;\n\t"                                    \
            "WAIT_LOOP_%=:\n\t"                                                   \
            "mbarrier.try_wait.parity.acquire.cta.shared::cta.b64 P1, [%0], %1, 0x989680;\n\t" \
            "@P1 bra.uni WAIT_DONE_%=;\n\t"                                       \
            "bra.uni WAIT_LOOP_%=;\n\t"                                           \
            "WAIT_DONE_%=:\n\t}"                                                  \
            :: "r"(_m), "r"(_p) : "memory");                                      \
    }                                                                             \
} while (0)

#define BULK_G2S(dst, src, bytes, mbar) \
    asm volatile("cp.async.bulk.shared::cluster.global.mbarrier::complete_tx::bytes " \
        "[%0], [%1], %2, [%3];" \
        :: "r"((uint32_t)(dst)), "l"(__cvta_generic_to_global(src)), \
           "r"((uint32_t)(bytes)), "r"((uint32_t)(mbar)) : "memory")

__device__ __forceinline__ void ldsm4(uint32_t r[4], uint32_t addr) {
    asm volatile("ldmatrix.sync.aligned.m8n8.x4.shared.b16 {%0,%1,%2,%3}, [%4];"
        : "=r"(r[0]), "=r"(r[1]), "=r"(r[2]), "=r"(r[3]) : "r"(addr));
}

__device__ __forceinline__ void mma16816(float d[4], const uint32_t a[4],
                                         uint32_t b0, uint32_t b1) {
    asm volatile("mma.sync.aligned.m16n8k16.row.col.f32.bf16.bf16.f32 "
        "{%0,%1,%2,%3}, {%4,%5,%6,%7}, {%8,%9}, {%0,%1,%2,%3};"
        : "+f"(d[0]), "+f"(d[1]), "+f"(d[2]), "+f"(d[3])
        : "r"(a[0]), "r"(a[1]), "r"(a[2]), "r"(a[3]), "r"(b0), "r"(b1));
}

__device__ __forceinline__ uint32_t pack_bf16x2(float hi, float lo) {
    uint32_t r;
    asm("cvt.rn.satfinite.bf16x2.f32 %0, %1, %2;" : "=r"(r) : "f"(hi), "f"(lo));
    return r;
}

// ---------------------------------------------------------------------------
// Gmem scratch
// g_qh[b][qt64][64 rows][64 bf16: hi(0..31)|lo(32..63)]   8KB/tile
// g_kh[b][kt32][128 rows][64 bf16: hi|lo]                 16KB/tile
// g_vh[b][kt32][256 ch][128 keys bf16]                    64KB/tile
// g_xh/g_xl[b][nt16][kc4][n256][k64 bf16]                 32KB/chunk, swizzled
// ---------------------------------------------------------------------------
__device__ __align__(16) unsigned char g_qh[(size_t)B_ * 64 * 8192];
__device__ __align__(16) unsigned char g_kh[(size_t)B_ * 32 * 16384];
__device__ __align__(16) unsigned char g_vh[(size_t)B_ * 32 * 65536];
__device__ __align__(16) unsigned char g_xh[(size_t)B_ * 16 * 4 * 32768];
__device__ __align__(16) unsigned char g_xl[(size_t)B_ * 16 * 4 * 32768];

// ---------------------------------------------------------------------------
// xcvt: x fp32 [b][c][n] -> hi/lo bf16, transposed + swizzled chunk tiles.
// grid (4 kc, 16 nt, 8 b), 256 threads. dyn smem 2 x [256][72] bf16.
// ---------------------------------------------------------------------------
#define XC_STRIDE 72
#define XC_SMEM   (2 * 256 * XC_STRIDE * 2)

__global__ __launch_bounds__(256, 1)
void xcvt_kernel(const float* __restrict__ x)
{
    extern __shared__ __align__(16) unsigned char xsm[];
    __nv_bfloat16* smh = (__nv_bfloat16*)xsm;
    __nv_bfloat16* sml = smh + 256 * XC_STRIDE;

    const int kc = blockIdx.x;
    const int nt = blockIdx.y;
    const int b  = blockIdx.z;
    const int tid = threadIdx.x;
    const int c0g = kc * 64;
    const int n0g = nt * 256;

    // read 4 channel-rows x 4 n, transpose into smem [n][c]
#pragma unroll
    for (int it = 0; it < 4; it++) {
        int lin = tid + 256 * it;       // 0..1023
        int c4  = lin >> 6;             // 0..15
        int f4  = lin & 63;             // n0 = f4*4
        int c0  = c4 * 4;
        float4 v[4];
#pragma unroll
        for (int r = 0; r < 4; r++)
            v[r] = *(const float4*)&x[((size_t)b * C_ + c0g + c0 + r) * N_ + n0g + f4 * 4];
#pragma unroll
        for (int nn = 0; nn < 4; nn++) {
            int n = f4 * 4 + nn;
            float fv[4] = {nn == 0 ? v[0].x : nn == 1 ? v[0].y : nn == 2 ? v[0].z : v[0].w,
                           nn == 0 ? v[1].x : nn == 1 ? v[1].y : nn == 2 ? v[1].z : v[1].w,
                           nn == 0 ? v[2].x : nn == 1 ? v[2].y : nn == 2 ? v[2].z : v[2].w,
                           nn == 0 ? v[3].x : nn == 1 ? v[3].y : nn == 2 ? v[3].z : v[3].w};
            __nv_bfloat16 h[4], l[4];
#pragma unroll
            for (int r = 0; r < 4; r++) {
                h[r] = __float2bfloat16(fv[r]);
                l[r] = __float2bfloat16(fv[r] - __bfloat162float(h[r]));
            }
            *(uint2*)&smh[n * XC_STRIDE + c0] = *(uint2*)h;
            *(uint2*)&sml[n * XC_STRIDE + c0] = *(uint2*)l;
        }
    }
    __syncthreads();

    // write out: [n256][k64] 128B rows, swizzle g^(n&7)
    const size_t base = (((size_t)b * 16 + nt) * 4 + kc) * 32768;
#pragma unroll
    for (int it = 0; it < 8; it++) {
        int id = tid + 256 * it;        // 0..2047
        int n  = id >> 3;
        int g  = id & 7;
        uint32_t off = n * 128 + ((g ^ (n & 7)) << 4);
        *(uint4*)(g_xh + base + off) = *(uint4*)&smh[n * XC_STRIDE + g * 8];
        *(uint4*)(g_xl + base + off) = *(uint4*)&sml[n * XC_STRIDE + g * 8];
    }
}

// ---------------------------------------------------------------------------
// proj_all: q/k/v = W @ x + b via mma.sync with hi/lo 3-term split.
// grid (16 nt, 5 mt, 8 b), 256 threads (8 warps: 4 m16-blocks x 2 n128-halves)
// mt0 = qk (rows 0-31 q, 32-63 k), mt1..4 = v rows (mt-1)*64..
// ---------------------------------------------------------------------------
#define PW_OFF   0u         // sW: [64 m][512 bf16 hi|lo], 1024B rows, 64KB
#define PX_OFF   65536u     // 4 x 32KB: buf0_h, buf0_l, buf1_h, buf1_l
#define PB_OFF   196608u    // bias 64 floats
#define PMB_OFF  196868u    // align 8: actually use 196872
#define P_SMEM   196896

__global__ __launch_bounds__(256, 1)
void proj_all_kernel(const float* __restrict__ x,
                     const float* __restrict__ wq, const float* __restrict__ bq,
                     const float* __restrict__ wk, const float* __restrict__ bk,
                     const float* __restrict__ wv, const float* __restrict__ bv)
{
    extern __shared__ __align__(1024) unsigned char psm[];
    const uint32_t sb = smem_u32(psm);
    const uint32_t mb0 = (sb + PMB_OFF + 7) & ~7u;
    const uint32_t mb1 = mb0 + 8;

    const int tid  = threadIdx.x;
    const int lane = tid & 31;
    const int w    = tid >> 5;
    const int nt   = blockIdx.x;
    const int mt   = blockIdx.y;
    const int b    = blockIdx.z;
    const int gr   = lane >> 2;
    const int tc   = lane & 3;

    float* sBias = (float*)(psm + PB_OFF);

    if (tid == 0) { MBARRIER_INIT(mb0, 1); MBARRIER_INIT(mb1, 1); }
    if (tid < 64) {
        sBias[tid] = (mt == 0) ? (tid < 32 ? bq[tid] : bk[tid - 32])
                               : bv[(mt - 1) * 64 + tid];
    }
    __syncthreads();

    // issue chunk 0
    const size_t xbase = ((size_t)b * 16 + nt) * 4 * 32768;
    if (tid == 0) {
        MBARRIER_EXPECT_TX(mb0, 65536);
        BULK_G2S(sb + PX_OFF + 0,     g_xh + xbase, 32768, mb0);
        BULK_G2S(sb + PX_OFF + 32768, g_xl + xbase, 32768, mb0);
    }

    // stage W: 64 rows x 256 fp32 -> sW [64][512 bf16 hi|lo] swizzled
#pragma unroll
    for (int it = 0; it < 8; it++) {
        int lin = tid + 256 * it;       // 0..2047 -> 8 floats each
        int row = lin >> 5;             // 0..63
        int f8  = lin & 31;             // c0 = f8*8
        int c0  = f8 * 8;
        const float* wp = (mt == 0)
            ? (row < 32 ? &wq[row * 256 + c0] : &wk[(row - 32) * 256 + c0])
            : &wv[(size_t)((mt - 1) * 64 + row) * 256 + c0];
        float4 v0 = *(const float4*)wp;
        float4 v1 = *(const float4*)(wp + 4);
        float fv[8] = {v0.x, v0.y, v0.z, v0.w, v1.x, v1.y, v1.z, v1.w};
        union { uint4 u; __nv_bfloat16 h[8]; } ph, pl;
#pragma unroll
        for (int j = 0; j < 8; j++) {
            ph.h[j] = __float2bfloat16(fv[j]);
            pl.h[j] = __float2bfloat16(fv[j] - __bfloat162float(ph.h[j]));
        }
        int gh = c0 >> 3;               // hi group 0..31
        int gl = 32 + gh;               // lo group
        *(uint4*)(psm + PW_OFF + row * 1024 + ((gh ^ (row & 7)) << 4)) = ph.u;
        *(uint4*)(psm + PW_OFF + row * 1024 + ((gl ^ (row & 7)) << 4)) = pl.u;
    }
    __syncthreads();

    float acc[16][4];
#pragma unroll
    for (int i = 0; i < 16; i++)
#pragma unroll
        for (int j = 0; j < 4; j++) acc[i][j] = 0.f;

    const int mrow = (w >> 1) * 16;     // warp m block
    const int nwp  = (w & 1) * 128;     // warp n block

    for (int c = 0; c < 4; c++) {
        if (c > 0) __syncthreads();     // all warps done with buf (c-1)&1
        if (tid == 0 && c < 3) {
            const uint32_t nmb = ((c + 1) & 1) ? mb1 : mb0;
            MBARRIER_EXPECT_TX(nmb, 65536);
            BULK_G2S(sb + PX_OFF + ((c + 1) & 1) * 65536,
                     g_xh + xbase + (size_t)(c + 1) * 32768, 32768, nmb);
            BULK_G2S(sb + PX_OFF + ((c + 1) & 1) * 65536 + 32768,
                     g_xl + xbase + (size_t)(c + 1) * 32768, 32768, nmb);
        }
        MBARRIER_WAIT_PARITY((c & 1) ? mb1 : mb0, (c >> 1) & 1);

        // A fragments for this k-chunk (hi and lo)
        uint32_t Ahi[4][4], Alo[4][4];
        {
            int row = mrow + (lane & 15);
            int sw  = row & 7;
            uint32_t rbase = sb + PW_OFF + row * 1024;
#pragma unroll
            for (int k16 = 0; k16 < 4; k16++) {
                int gh = (c * 64 + k16 * 16) >> 3;      // 16 bf16 = 2 groups
                int g  = gh + (lane >> 4);
                ldsm4(Ahi[k16], rbase + ((g ^ sw) << 4));
                ldsm4(Alo[k16], rbase + (((32 + g) ^ sw) << 4));
            }
        }

        const uint32_t xh = sb + PX_OFF + (c & 1) * 65536;
        const uint32_t xl = xh + 32768;
#pragma unroll
        for (int nb = 0; nb < 16; nb++) {
            uint32_t Bh[8], Bl[8];
            int row = nwp + nb * 8 + (lane & 7);
            int sw  = row & 7;
            int ga  = lane >> 3;
            ldsm4(Bh,     xh + row * 128 + ((ga ^ sw) << 4));
            ldsm4(Bh + 4, xh + row * 128 + (((4 + ga) ^ sw) << 4));
            ldsm4(Bl,     xl + row * 128 + ((ga ^ sw) << 4));
            ldsm4(Bl + 4, xl + row * 128 + (((4 + ga) ^ sw) << 4));
#pragma unroll
            for (int k16 = 0; k16 < 4; k16++) {
                mma16816(acc[nb], Ahi[k16], Bh[2 * k16], Bh[2 * k16 + 1]);
                mma16816(acc[nb], Ahi[k16], Bl[2 * k16], Bl[2 * k16 + 1]);
                mma16816(acc[nb], Alo[k16], Bh[2 * k16], Bh[2 * k16 + 1]);
            }
        }
    }
    __syncthreads();

    // stage accum to smem [64 m][260 n stride] fp32 (reuse sX region)
    float* st = (float*)(psm + PX_OFF);
#pragma unroll
    for (int nb = 0; nb < 16; nb++) {
        int ncol = nwp + nb * 8 + tc * 2;
        *(float2*)&st[(mrow + gr) * 260 + ncol]     = make_float2(acc[nb][0], acc[nb][1]);
        *(float2*)&st[(mrow + gr + 8) * 260 + ncol] = make_float2(acc[nb][2], acc[nb][3]);
    }
    __syncthreads();

    if (mt == 0) {
        // q rows 0..31 -> g_qh (64-row tiles), k rows 32..63 -> g_kh (128-row)
#pragma unroll
        for (int it = 0; it < 16; it++) {
            int id    = tid + 256 * it;      // 0..4095
            int which = id >> 11;            // 0=q 1=k
            int m2    = id & 2047;
            int nrow  = m2 >> 3;             // 0..255 (n within tile-256)
            int g     = m2 & 7;
            int o0    = (g & 3) * 8;
            bool islo = g >= 4;
            union { uint4 u; __nv_bfloat16 h[8]; } pk;
#pragma unroll
            for (int j = 0; j < 8; j++) {
                float v = st[(which * 32 + o0 + j) * 260 + nrow]
                        + sBias[which * 32 + o0 + j];
                __nv_bfloat16 hi = __float2bfloat16(v);
                pk.h[j] = islo ? __float2bfloat16(v - __bfloat162float(hi)) : hi;
            }
            unsigned char* dst;
            if (which) {
                int tile = nt * 2 + (nrow >> 7);
                int r    = nrow & 127;
                dst = g_kh + ((size_t)(b * 32 + tile)) * 16384
                    + r * 128 + ((g ^ (r & 7)) << 4);
            } else {
                int tile = nt * 4 + (nrow >> 6);
                int r    = nrow & 63;
                dst = g_qh + ((size_t)(b * 64 + tile)) * 8192
                    + r * 128 + ((g ^ (r & 7)) << 4);
            }
            *(uint4*)dst = pk.u;
        }
    } else {
        // v rows -> g_vh [ch][key] tiles
        const int ch0 = (mt - 1) * 64;
#pragma unroll
        for (int it = 0; it < 8; it++) {
            int id  = tid + 256 * it;        // 0..2047
            int chl = id >> 5;               // 0..63
            int kg  = id & 31;               // n-group within 256
            int chg = ch0 + chl;
            float bb = sBias[chl];
            union { uint4 u; __nv_bfloat16 h[8]; } pk;
#pragma unroll
            for (int j = 0; j < 8; j++)
                pk.h[j] = __float2bfloat16(st[chl * 260 + kg * 8 + j] + bb);
            int tile = nt * 2 + (kg >> 4);
            int kgl  = kg & 15;
            *(uint4*)(g_vh + ((size_t)(b * 32 + tile)) * 65536
                      + chg * 256 + ((kgl ^ (chg & 7)) << 4)) = pk.u;
        }
    }
}

// ---------------------------------------------------------------------------
// Attention: mma.sync flash attention, 64 queries/CTA, grid (64, 8), 256 thr
// (unchanged from round 4)
// ---------------------------------------------------------------------------
#define SQ_  0u
#define SK_  8192u
#define SV_  40960u
#define SP_  172032u          // 64 rows * 272 B
#define SL_  189440u          // 64 floats
#define SMB_ 189696u          // 2 mbarriers
#define SMEM_TOTAL 189952

__global__ __launch_bounds__(256, 1)
void attn_kernel(const float* __restrict__ x,
                 const float* __restrict__ gamma,
                 float* __restrict__ y)
{
    extern __shared__ __align__(16) unsigned char smem[];
    const uint32_t sb = smem_u32(smem);
    const int tid  = threadIdx.x;
    const int lane = tid & 31;
    const int w    = tid >> 5;
    const int b    = blockIdx.y;
    const int qt   = blockIdx.x;
    const int ib   = w >> 1;
    const int half = w & 1;
    const int gr   = lane >> 2;
    const int tc   = lane & 3;

    if (tid < 64) *(float*)(smem + SL_ + tid * 4) = 0.f;
    if (tid == 0) {
        MBARRIER_INIT(sb + SMB_ + 0, 1);
        MBARRIER_INIT(sb + SMB_ + 8, 1);
    }
    __syncthreads();

    const unsigned char* gq  = g_qh + ((size_t)(b * 64 + qt)) * 8192;
    const unsigned char* gk0 = g_kh + ((size_t)b * 32) * 16384;
    const unsigned char* gv0 = g_vh + ((size_t)b * 32) * 65536;

    if (tid == 0) {
        MBARRIER_EXPECT_TX(sb + SMB_ + 0, 8192 + 16384 + 65536);
        BULK_G2S(sb + SQ_, gq, 8192, sb + SMB_ + 0);
        BULK_G2S(sb + SK_, gk0, 16384, sb + SMB_ + 0);
        BULK_G2S(sb + SV_, gv0, 65536, sb + SMB_ + 0);
    }

    float accs[16][4];
#pragma unroll
    for (int i = 0; i < 16; i++)
#pragma unroll
        for (int j = 0; j < 4; j++) accs[i][j] = 0.f;

    uint32_t Qa[4][4];
    float lsA = 0.f, lsB = 0.f;

    for (int jt = 0; jt < 32; jt++) {
        const int buf = jt & 1;

        if (tid == 0 && jt < 31) {
            const int nb = (jt + 1) & 1;
            MBARRIER_EXPECT_TX(sb + SMB_ + 8 * nb, 16384 + 65536);
            BULK_G2S(sb + SK_ + nb * 16384, gk0 + (size_t)(jt + 1) * 16384,
                     16384, sb + SMB_ + 8 * nb);
            BULK_G2S(sb + SV_ + nb * 65536, gv0 + (size_t)(jt + 1) * 65536,
                     65536, sb + SMB_ + 8 * nb);
        }

        MBARRIER_WAIT_PARITY(sb + SMB_ + 8 * buf, (jt >> 1) & 1);

        if (jt == 0) {
#pragma unroll
            for (int c = 0; c < 4; c++) {
                int row = ib * 16 + (lane & 15);
                int g   = 2 * c + (lane >> 4);
                ldsm4(Qa[c], sb + SQ_ + row * 128 + ((g ^ (row & 7)) << 4));
            }
        }

        const uint32_t kbase = sb + SK_ + buf * 16384;
#pragma unroll
        for (int nf = 0; nf < 8; nf += 2) {
            uint32_t kb0[8], kb1[8];
            {
                int j0 = half * 64 + nf * 8 + (lane & 7);
                int j1 = j0 + 8;
                int ga = (lane >> 3), gb = 4 + (lane >> 3);
                ldsm4(kb0,     kbase + j0 * 128 + ((ga ^ (j0 & 7)) << 4));
                ldsm4(kb0 + 4, kbase + j0 * 128 + ((gb ^ (j0 & 7)) << 4));
                ldsm4(kb1,     kbase + j1 * 128 + ((ga ^ (j1 & 7)) << 4));
                ldsm4(kb1 + 4, kbase + j1 * 128 + ((gb ^ (j1 & 7)) << 4));
            }
            float d0[4] = {0.f, 0.f, 0.f, 0.f};
            float d1[4] = {0.f, 0.f, 0.f, 0.f};
#pragma unroll
            for (int c = 0; c < 4; c++) {
                mma16816(d0, Qa[c], kb0[2 * c], kb0[2 * c + 1]);
                mma16816(d1, Qa[c], kb1[2 * c], kb1[2 * c + 1]);
                mma16816(d0, Qa[c], kb0[(2 * c + 4) & 7], kb0[(2 * c + 5) & 7]);
                mma16816(d1, Qa[c], kb1[(2 * c + 4) & 7], kb1[(2 * c + 5) & 7]);
            }
#pragma unroll
            for (int q2 = 0; q2 < 2; q2++) {
                float* d = q2 ? d1 : d0;
                float e0 = __expf(d[0]), e1 = __expf(d[1]);
                float e2 = __expf(d[2]), e3 = __expf(d[3]);
                lsA += e0 + e1;
                lsB += e2 + e3;
                int colb = (half * 64 + (nf + q2) * 8 + tc * 2) * 2;
                int r0   = ib * 16 + gr;
                *(uint32_t*)(smem + SP_ + r0 * 272 + colb)       = pack_bf16x2(e1, e0);
                *(uint32_t*)(smem + SP_ + (r0 + 8) * 272 + colb) = pack_bf16x2(e3, e2);
            }
        }
        __syncthreads();

        uint32_t Pa[8][4];
#pragma unroll
        for (int kc = 0; kc < 8; kc++) {
            int row = ib * 16 + (lane & 15);
            int cb  = kc * 16 + (lane >> 4) * 8;
            ldsm4(Pa[kc], sb + SP_ + row * 272 + cb * 2);
        }
        const uint32_t vbase = sb + SV_ + buf * 65536;
#pragma unroll
        for (int nf = 0; nf < 16; nf += 2) {
            uint32_t vb0[16], vb1[16];
            {
                int ch0 = half * 128 + nf * 8 + (lane & 7);
                int ch1 = ch0 + 8;
#pragma unroll
                for (int p = 0; p < 4; p++) {
                    int g = 4 * p + (lane >> 3);
                    ldsm4(vb0 + 4 * p, vbase + ch0 * 256 + ((g ^ (ch0 & 7)) << 4));
                    ldsm4(vb1 + 4 * p, vbase + ch1 * 256 + ((g ^ (ch1 & 7)) << 4));
                }
            }
#pragma unroll
            for (int kc = 0; kc < 8; kc++) {
                mma16816(accs[nf],     Pa[kc], vb0[2 * kc], vb0[2 * kc + 1]);
                mma16816(accs[nf + 1], Pa[kc], vb1[2 * kc], vb1[2 * kc + 1]);
            }
        }
        __syncthreads();
    }

    lsA += __shfl_xor_sync(0xffffffffu, lsA, 1);
    lsA += __shfl_xor_sync(0xffffffffu, lsA, 2);
    lsB += __shfl_xor_sync(0xffffffffu, lsB, 1);
    lsB += __shfl_xor_sync(0xffffffffu, lsB, 2);
    if (tc == 0) {
        atomicAdd((float*)(smem + SL_ + (ib * 16 + gr) * 4), lsA);
        atomicAdd((float*)(smem + SL_ + (ib * 16 + gr + 8) * 4), lsB);
    }
    __syncthreads();

    const float gm = gamma[0];
    const int r0   = ib * 16 + gr;
    const float inv0 = 1.0f / *(float*)(smem + SL_ + r0 * 4);
    const float inv8 = 1.0f / *(float*)(smem + SL_ + (r0 + 8) * 4);
    const int i0 = qt * 64;
#pragma unroll
    for (int nf = 0; nf < 16; nf++) {
        int c = half * 128 + nf * 8 + tc * 2;
        size_t base0 = ((size_t)b * C_ + c) * N_ + i0;
        size_t base1 = base0 + N_;
        y[base0 + r0]     = gm * accs[nf][0] * inv0 + x[base0 + r0];
        y[base1 + r0]     = gm * accs[nf][1] * inv0 + x[base1 + r0];
        y[base0 + r0 + 8] = gm * accs[nf][2] * inv8 + x[base0 + r0 + 8];
        y[base1 + r0 + 8] = gm * accs[nf][3] * inv8 + x[base1 + r0 + 8];
    }
}

// ---------------------------------------------------------------------------
extern "C" void kernel_launch(void* const* d_in, const int* in_sizes, int n_in,
                              void* d_out, int out_size)
{
    const float* x     = (const float*)d_in[0];
    const float* wq    = (const float*)d_in[1];
    const float* bq    = (const float*)d_in[2];
    const float* wk    = (const float*)d_in[3];
    const float* bk    = (const float*)d_in[4];
    const float* wv    = (const float*)d_in[5];
    const float* bv    = (const float*)d_in[6];
    const float* gamma = (const float*)d_in[7];
    float* y = (float*)d_out;

    cudaFuncSetAttribute(xcvt_kernel,
                         cudaFuncAttributeMaxDynamicSharedMemorySize, XC_SMEM);
    cudaFuncSetAttribute(proj_all_kernel,
                         cudaFuncAttributeMaxDynamicSharedMemorySize, P_SMEM);
    cudaFuncSetAttribute(attn_kernel,
                         cudaFuncAttributeMaxDynamicSharedMemorySize, SMEM_TOTAL);

    xcvt_kernel    <<<dim3(4, 16, B_), 256, XC_SMEM>>>(x);
    proj_all_kernel<<<dim3(16, 5, B_), 256, P_SMEM>>>(x, wq, bq, wk, bk, wv, bv);
    attn_kernel    <<<dim3(64, B_), 256, SMEM_TOTAL>>>(x, gamma, y);
}

// round 6
// speedup vs baseline: 7.5893x; 1.0851x over previous
#include <cuda_runtime.h>
#include <cuda_bf16.h>
#include <stdint.h>

#define B_   8
#define C_   256
#define N_   4096
#define CQ_  32

// ---------------------------------------------------------------------------
// PTX helpers (sm_80/sm_90-class only -- NO tcgen05)
// ---------------------------------------------------------------------------
__device__ __forceinline__ uint32_t smem_u32(const void* p) {
    uint32_t a;
    asm("{ .reg .u64 t; cvta.to.shared.u64 t, %1; cvt.u32.u64 %0, t; }"
        : "=r"(a) : "l"(p));
    return a;
}

#define MBARRIER_INIT(mbar, count) \
    asm volatile("mbarrier.init.shared.b64 [%0], %1;" \
        :: "r"((uint32_t)(mbar)), "r"((uint32_t)(count)) : "memory")
#define MBARRIER_EXPECT_TX(mbar, bytes) \
    asm volatile("mbarrier.arrive.expect_tx.shared.b64 _, [%0], %1;" \
        :: "r"((uint32_t)(mbar)), "r"((uint32_t)(bytes)) : "memory")

#define MBARRIER_WAIT_PARITY(mbar, parity) do {                                   \
    uint32_t _m = (uint32_t)(mbar); uint32_t _p = (uint32_t)(parity);             \
    uint32_t _done;                                                               \
    asm volatile("{\n\t.reg .pred p;\n\t"                                         \
        "mbarrier.try_wait.parity.acquire.cta.shared::cta.b64 p, [%1], %2;\n\t"   \
        "selp.b32 %0, 1, 0, p;\n\t}"                                              \
        : "=r"(_done) : "r"(_m), "r"(_p) : "memory");                             \
    if (!_done) {                                                                 \
        asm volatile("{\n\t.reg .pred P1;\n\t"                                    \
            "WAIT_LOOP_%=:\n\t"                                                   \
            "mbarrier.try_wait.parity.acquire.cta.shared::cta.b64 P1, [%0], %1, 0x989680;\n\t" \
            "@P1 bra.uni WAIT_DONE_%=;\n\t"                                       \
            "bra.uni WAIT_LOOP_%=;\n\t"                                           \
            "WAIT_DONE_%=:\n\t}"                                                  \
            :: "r"(_m), "r"(_p) : "memory");                                      \
    }                                                                             \
} while (0)

#define BULK_G2S(dst, src, bytes, mbar) \
    asm volatile("cp.async.bulk.shared::cluster.global.mbarrier::complete_tx::bytes " \
        "[%0], [%1], %2, [%3];" \
        :: "r"((uint32_t)(dst)), "l"(__cvta_generic_to_global(src)), \
           "r"((uint32_t)(bytes)), "r"((uint32_t)(mbar)) : "memory")

__device__ __forceinline__ void ldsm4(uint32_t r[4], uint32_t addr) {
    asm volatile("ldmatrix.sync.aligned.m8n8.x4.shared.b16 {%0,%1,%2,%3}, [%4];"
        : "=r"(r[0]), "=r"(r[1]), "=r"(r[2]), "=r"(r[3]) : "r"(addr));
}

__device__ __forceinline__ void mma16816(float d[4], const uint32_t a[4],
                                         uint32_t b0, uint32_t b1) {
    asm volatile("mma.sync.aligned.m16n8k16.row.col.f32.bf16.bf16.f32 "
        "{%0,%1,%2,%3}, {%4,%5,%6,%7}, {%8,%9}, {%0,%1,%2,%3};"
        : "+f"(d[0]), "+f"(d[1]), "+f"(d[2]), "+f"(d[3])
        : "r"(a[0]), "r"(a[1]), "r"(a[2]), "r"(a[3]), "r"(b0), "r"(b1));
}

__device__ __forceinline__ uint32_t pack_bf16x2(float hi, float lo) {
    uint32_t r;
    asm("cvt.rn.satfinite.bf16x2.f32 %0, %1, %2;" : "=r"(r) : "f"(hi), "f"(lo));
    return r;
}

// ---------------------------------------------------------------------------
// Gmem scratch
// ---------------------------------------------------------------------------
__device__ __align__(16) unsigned char g_qh[(size_t)B_ * 64 * 8192];
__device__ __align__(16) unsigned char g_kh[(size_t)B_ * 32 * 16384];
__device__ __align__(16) unsigned char g_vh[(size_t)B_ * 32 * 65536];
__device__ __align__(16) unsigned char g_xh[(size_t)B_ * 16 * 4 * 32768];
__device__ __align__(16) unsigned char g_xl[(size_t)B_ * 16 * 4 * 32768];

// ---------------------------------------------------------------------------
// xcvt: x fp32 [b][c][n] -> hi/lo bf16, transposed + swizzled chunk tiles.
// grid (4 kc, 16 nt, 8 b), 256 threads.
// ---------------------------------------------------------------------------
#define XC_STRIDE 72
#define XC_SMEM   (2 * 256 * XC_STRIDE * 2)

__global__ __launch_bounds__(256, 1)
void xcvt_kernel(const float* __restrict__ x)
{
    extern __shared__ __align__(16) unsigned char xsm[];
    __nv_bfloat16* smh = (__nv_bfloat16*)xsm;
    __nv_bfloat16* sml = smh + 256 * XC_STRIDE;

    const int kc = blockIdx.x;
    const int nt = blockIdx.y;
    const int b  = blockIdx.z;
    const int tid = threadIdx.x;
    const int c0g = kc * 64;
    const int n0g = nt * 256;

#pragma unroll
    for (int it = 0; it < 4; it++) {
        int lin = tid + 256 * it;
        int c4  = lin >> 6;
        int f4  = lin & 63;
        int c0  = c4 * 4;
        float4 v[4];
#pragma unroll
        for (int r = 0; r < 4; r++)
            v[r] = *(const float4*)&x[((size_t)b * C_ + c0g + c0 + r) * N_ + n0g + f4 * 4];
#pragma unroll
        for (int nn = 0; nn < 4; nn++) {
            int n = f4 * 4 + nn;
            float fv[4] = {nn == 0 ? v[0].x : nn == 1 ? v[0].y : nn == 2 ? v[0].z : v[0].w,
                           nn == 0 ? v[1].x : nn == 1 ? v[1].y : nn == 2 ? v[1].z : v[1].w,
                           nn == 0 ? v[2].x : nn == 1 ? v[2].y : nn == 2 ? v[2].z : v[2].w,
                           nn == 0 ? v[3].x : nn == 1 ? v[3].y : nn == 2 ? v[3].z : v[3].w};
            __nv_bfloat16 h[4], l[4];
#pragma unroll
            for (int r = 0; r < 4; r++) {
                h[r] = __float2bfloat16(fv[r]);
                l[r] = __float2bfloat16(fv[r] - __bfloat162float(h[r]));
            }
            *(uint2*)&smh[n * XC_STRIDE + c0] = *(uint2*)h;
            *(uint2*)&sml[n * XC_STRIDE + c0] = *(uint2*)l;
        }
    }
    __syncthreads();

    const size_t base = (((size_t)b * 16 + nt) * 4 + kc) * 32768;
#pragma unroll
    for (int it = 0; it < 8; it++) {
        int id = tid + 256 * it;
        int n  = id >> 3;
        int g  = id & 7;
        uint32_t off = n * 128 + ((g ^ (n & 7)) << 4);
        *(uint4*)(g_xh + base + off) = *(uint4*)&smh[n * XC_STRIDE + g * 8];
        *(uint4*)(g_xl + base + off) = *(uint4*)&sml[n * XC_STRIDE + g * 8];
    }
}

// ---------------------------------------------------------------------------
// proj_all: q/k/v = W @ x + b via mma.sync (hi/lo 3-term split).
// grid (16 nt, 5 mt, 8 b), 512 threads (16 warps: 4 m16 x 4 n64 tiles).
// ---------------------------------------------------------------------------
#define PW_OFF   0u         // sW: [64 m][512 bf16 hi|lo], 1024B rows, 64KB
#define PX_OFF   65536u     // 2 x (32KB hi + 32KB lo)
#define PB_OFF   196608u    // bias 64 floats
#define PMB_OFF  196872u
#define P_SMEM   196896

__global__ __launch_bounds__(512, 1)
void proj_all_kernel(const float* __restrict__ x,
                     const float* __restrict__ wq, const float* __restrict__ bq,
                     const float* __restrict__ wk, const float* __restrict__ bk,
                     const float* __restrict__ wv, const float* __restrict__ bv)
{
    extern __shared__ __align__(1024) unsigned char psm[];
    const uint32_t sb = smem_u32(psm);
    const uint32_t mb0 = sb + PMB_OFF;
    const uint32_t mb1 = mb0 + 8;

    const int tid  = threadIdx.x;
    const int lane = tid & 31;
    const int w    = tid >> 5;
    const int nt   = blockIdx.x;
    const int mt   = blockIdx.y;
    const int b    = blockIdx.z;
    const int gr   = lane >> 2;
    const int tc   = lane & 3;

    float* sBias = (float*)(psm + PB_OFF);

    if (tid == 0) { MBARRIER_INIT(mb0, 1); MBARRIER_INIT(mb1, 1); }
    if (tid < 64) {
        sBias[tid] = (mt == 0) ? (tid < 32 ? bq[tid] : bk[tid - 32])
                               : bv[(mt - 1) * 64 + tid];
    }
    __syncthreads();

    const size_t xbase = ((size_t)b * 16 + nt) * 4 * 32768;
    if (tid == 0) {
        MBARRIER_EXPECT_TX(mb0, 65536);
        BULK_G2S(sb + PX_OFF + 0,     g_xh + xbase, 32768, mb0);
        BULK_G2S(sb + PX_OFF + 32768, g_xl + xbase, 32768, mb0);
    }

    // stage W: 64 rows x 256 fp32 -> sW [64][512 bf16 hi|lo] swizzled
#pragma unroll
    for (int it = 0; it < 4; it++) {
        int lin = tid + 512 * it;       // 0..2047
        int row = lin >> 5;
        int f8  = lin & 31;
        int c0  = f8 * 8;
        const float* wp = (mt == 0)
            ? (row < 32 ? &wq[row * 256 + c0] : &wk[(row - 32) * 256 + c0])
            : &wv[(size_t)((mt - 1) * 64 + row) * 256 + c0];
        float4 v0 = *(const float4*)wp;
        float4 v1 = *(const float4*)(wp + 4);
        float fv[8] = {v0.x, v0.y, v0.z, v0.w, v1.x, v1.y, v1.z, v1.w};
        union { uint4 u; __nv_bfloat16 h[8]; } ph, pl;
#pragma unroll
        for (int j = 0; j < 8; j++) {
            ph.h[j] = __float2bfloat16(fv[j]);
            pl.h[j] = __float2bfloat16(fv[j] - __bfloat162float(ph.h[j]));
        }
        int gh = c0 >> 3;
        int gl = 32 + gh;
        *(uint4*)(psm + PW_OFF + row * 1024 + ((gh ^ (row & 7)) << 4)) = ph.u;
        *(uint4*)(psm + PW_OFF + row * 1024 + ((gl ^ (row & 7)) << 4)) = pl.u;
    }
    __syncthreads();

    float acc[8][4];
#pragma unroll
    for (int i = 0; i < 8; i++)
#pragma unroll
        for (int j = 0; j < 4; j++) acc[i][j] = 0.f;

    const int mrow = (w >> 2) * 16;     // warp m block (0..3)
    const int nwp  = (w & 3) * 64;      // warp n block (0..3)

    for (int c = 0; c < 4; c++) {
        if (c > 0) __syncthreads();
        if (tid == 0 && c < 3) {
            const uint32_t nmb = ((c + 1) & 1) ? mb1 : mb0;
            MBARRIER_EXPECT_TX(nmb, 65536);
            BULK_G2S(sb + PX_OFF + ((c + 1) & 1) * 65536,
                     g_xh + xbase + (size_t)(c + 1) * 32768, 32768, nmb);
            BULK_G2S(sb + PX_OFF + ((c + 1) & 1) * 65536 + 32768,
                     g_xl + xbase + (size_t)(c + 1) * 32768, 32768, nmb);
        }
        MBARRIER_WAIT_PARITY((c & 1) ? mb1 : mb0, (c >> 1) & 1);

        uint32_t Ahi[4][4], Alo[4][4];
        {
            int row = mrow + (lane & 15);
            int sw  = row & 7;
            uint32_t rbase = sb + PW_OFF + row * 1024;
#pragma unroll
            for (int k16 = 0; k16 < 4; k16++) {
                int gh = (c * 64 + k16 * 16) >> 3;
                int g  = gh + (lane >> 4);
                ldsm4(Ahi[k16], rbase + ((g ^ sw) << 4));
                ldsm4(Alo[k16], rbase + (((32 + g) ^ sw) << 4));
            }
        }

        const uint32_t xh = sb + PX_OFF + (c & 1) * 65536;
        const uint32_t xl = xh + 32768;
#pragma unroll
        for (int nb = 0; nb < 8; nb++) {
            uint32_t Bh[8], Bl[8];
            int row = nwp + nb * 8 + (lane & 7);
            int sw  = row & 7;
            int ga  = lane >> 3;
            ldsm4(Bh,     xh + row * 128 + ((ga ^ sw) << 4));
            ldsm4(Bh + 4, xh + row * 128 + (((4 + ga) ^ sw) << 4));
            ldsm4(Bl,     xl + row * 128 + ((ga ^ sw) << 4));
            ldsm4(Bl + 4, xl + row * 128 + (((4 + ga) ^ sw) << 4));
#pragma unroll
            for (int k16 = 0; k16 < 4; k16++) {
                mma16816(acc[nb], Ahi[k16], Bh[2 * k16], Bh[2 * k16 + 1]);
                mma16816(acc[nb], Ahi[k16], Bl[2 * k16], Bl[2 * k16 + 1]);
                mma16816(acc[nb], Alo[k16], Bh[2 * k16], Bh[2 * k16 + 1]);
            }
        }
    }
    __syncthreads();

    // stage accum to smem [64 m][260 n] fp32
    float* st = (float*)(psm + PX_OFF);
#pragma unroll
    for (int nb = 0; nb < 8; nb++) {
        int ncol = nwp + nb * 8 + tc * 2;
        *(float2*)&st[(mrow + gr) * 260 + ncol]     = make_float2(acc[nb][0], acc[nb][1]);
        *(float2*)&st[(mrow + gr + 8) * 260 + ncol] = make_float2(acc[nb][2], acc[nb][3]);
    }
    __syncthreads();

    if (mt == 0) {
#pragma unroll
        for (int it = 0; it < 8; it++) {
            int id    = tid + 512 * it;      // 0..4095
            int which = id >> 11;
            int m2    = id & 2047;
            int nrow  = m2 >> 3;
            int g     = m2 & 7;
            int o0    = (g & 3) * 8;
            bool islo = g >= 4;
            union { uint4 u; __nv_bfloat16 h[8]; } pk;
#pragma unroll
            for (int j = 0; j < 8; j++) {
                float v = st[(which * 32 + o0 + j) * 260 + nrow]
                        + sBias[which * 32 + o0 + j];
                __nv_bfloat16 hi = __float2bfloat16(v);
                pk.h[j] = islo ? __float2bfloat16(v - __bfloat162float(hi)) : hi;
            }
            unsigned char* dst;
            if (which) {
                int tile = nt * 2 + (nrow >> 7);
                int r    = nrow & 127;
                dst = g_kh + ((size_t)(b * 32 + tile)) * 16384
                    + r * 128 + ((g ^ (r & 7)) << 4);
            } else {
                int tile = nt * 4 + (nrow >> 6);
                int r    = nrow & 63;
                dst = g_qh + ((size_t)(b * 64 + tile)) * 8192
                    + r * 128 + ((g ^ (r & 7)) << 4);
            }
            *(uint4*)dst = pk.u;
        }
    } else {
        const int ch0 = (mt - 1) * 64;
#pragma unroll
        for (int it = 0; it < 4; it++) {
            int id  = tid + 512 * it;        // 0..2047
            int chl = id >> 5;
            int kg  = id & 31;
            int chg = ch0 + chl;
            float bb = sBias[chl];
            union { uint4 u; __nv_bfloat16 h[8]; } pk;
#pragma unroll
            for (int j = 0; j < 8; j++)
                pk.h[j] = __float2bfloat16(st[chl * 260 + kg * 8 + j] + bb);
            int tile = nt * 2 + (kg >> 4);
            int kgl  = kg & 15;
            *(uint4*)(g_vh + ((size_t)(b * 32 + tile)) * 65536
                      + chg * 256 + ((kgl ^ (chg & 7)) << 4)) = pk.u;
        }
    }
}

// ---------------------------------------------------------------------------
// Attention: mma.sync flash attention, 64 queries/CTA, grid (64, 8), 256 thr
// 3-term GEMM1, double-buffered P, one syncthreads per tile.
// ---------------------------------------------------------------------------
#define SQ_  0u
#define SK_  8192u
#define SV_  40960u
#define SP0_ 172032u          // P buf0: 64 rows * 272 B
#define SP1_ 189440u          // P buf1
#define SL_  206848u          // 64 floats
#define SMB_ 207104u          // 2 mbarriers
#define SMEM_TOTAL 207136

__global__ __launch_bounds__(256, 1)
void attn_kernel(const float* __restrict__ x,
                 const float* __restrict__ gamma,
                 float* __restrict__ y)
{
    extern __shared__ __align__(16) unsigned char smem[];
    const uint32_t sb = smem_u32(smem);
    const int tid  = threadIdx.x;
    const int lane = tid & 31;
    const int w    = tid >> 5;
    const int b    = blockIdx.y;
    const int qt   = blockIdx.x;
    const int ib   = w >> 1;
    const int half = w & 1;
    const int gr   = lane >> 2;
    const int tc   = lane & 3;

    if (tid < 64) *(float*)(smem + SL_ + tid * 4) = 0.f;
    if (tid == 0) {
        MBARRIER_INIT(sb + SMB_ + 0, 1);
        MBARRIER_INIT(sb + SMB_ + 8, 1);
    }
    __syncthreads();

    const unsigned char* gq  = g_qh + ((size_t)(b * 64 + qt)) * 8192;
    const unsigned char* gk0 = g_kh + ((size_t)b * 32) * 16384;
    const unsigned char* gv0 = g_vh + ((size_t)b * 32) * 65536;

    // prologue: Q + tiles 0,1
    if (tid == 0) {
        MBARRIER_EXPECT_TX(sb + SMB_ + 0, 8192 + 16384 + 65536);
        BULK_G2S(sb + SQ_, gq, 8192, sb + SMB_ + 0);
        BULK_G2S(sb + SK_, gk0, 16384, sb + SMB_ + 0);
        BULK_G2S(sb + SV_, gv0, 65536, sb + SMB_ + 0);
        MBARRIER_EXPECT_TX(sb + SMB_ + 8, 16384 + 65536);
        BULK_G2S(sb + SK_ + 16384, gk0 + 16384, 16384, sb + SMB_ + 8);
        BULK_G2S(sb + SV_ + 65536, gv0 + 65536, 65536, sb + SMB_ + 8);
    }

    float accs[16][4];
#pragma unroll
    for (int i = 0; i < 16; i++)
#pragma unroll
        for (int j = 0; j < 4; j++) accs[i][j] = 0.f;

    uint32_t Qa[4][4];
    float lsA = 0.f, lsB = 0.f;

    for (int jt = 0; jt < 32; jt++) {
        const int buf = jt & 1;
        const uint32_t pbuf = buf ? SP1_ : SP0_;

        MBARRIER_WAIT_PARITY(sb + SMB_ + 8 * buf, (jt >> 1) & 1);

        if (jt == 0) {
#pragma unroll
            for (int c = 0; c < 4; c++) {
                int row = ib * 16 + (lane & 15);
                int g   = 2 * c + (lane >> 4);
                ldsm4(Qa[c], sb + SQ_ + row * 128 + ((g ^ (row & 7)) << 4));
            }
        }

        // ---- GEMM1 (3-term) + exp + P store ----
        const uint32_t kbase = sb + SK_ + buf * 16384;
#pragma unroll
        for (int nf = 0; nf < 8; nf += 2) {
            uint32_t kb0[8], kb1[8];
            {
                int j0 = half * 64 + nf * 8 + (lane & 7);
                int j1 = j0 + 8;
                int ga = (lane >> 3), gb = 4 + (lane >> 3);
                ldsm4(kb0,     kbase + j0 * 128 + ((ga ^ (j0 & 7)) << 4));
                ldsm4(kb0 + 4, kbase + j0 * 128 + ((gb ^ (j0 & 7)) << 4));
                ldsm4(kb1,     kbase + j1 * 128 + ((ga ^ (j1 & 7)) << 4));
                ldsm4(kb1 + 4, kbase + j1 * 128 + ((gb ^ (j1 & 7)) << 4));
            }
            float d0[4] = {0.f, 0.f, 0.f, 0.f};
            float d1[4] = {0.f, 0.f, 0.f, 0.f};
#pragma unroll
            for (int c = 0; c < 4; c++) {
                if (c < 2) {   // hi*hi (c<2); lo*lo dropped
                    mma16816(d0, Qa[c], kb0[2 * c], kb0[2 * c + 1]);
                    mma16816(d1, Qa[c], kb1[2 * c], kb1[2 * c + 1]);
                }
                // hi*lo (c=0,1) and lo*hi (c=2,3)
                mma16816(d0, Qa[c], kb0[(2 * c + 4) & 7], kb0[(2 * c + 5) & 7]);
                mma16816(d1, Qa[c], kb1[(2 * c + 4) & 7], kb1[(2 * c + 5) & 7]);
            }
#pragma unroll
            for (int q2 = 0; q2 < 2; q2++) {
                float* d = q2 ? d1 : d0;
                float e0 = __expf(d[0]), e1 = __expf(d[1]);
                float e2 = __expf(d[2]), e3 = __expf(d[3]);
                lsA += e0 + e1;
                lsB += e2 + e3;
                int colb = (half * 64 + (nf + q2) * 8 + tc * 2) * 2;
                int r0   = ib * 16 + gr;
                *(uint32_t*)(smem + pbuf + r0 * 272 + colb)       = pack_bf16x2(e1, e0);
                *(uint32_t*)(smem + pbuf + (r0 + 8) * 272 + colb) = pack_bf16x2(e3, e2);
            }
        }
        __syncthreads();   // P(jt) complete; all warps past GEMM2(jt-1)

        // safe now: buffer (jt+1)&1 fully consumed (K in GEMM1(jt-1), V in GEMM2(jt-1))
        if (tid == 0 && jt >= 1 && jt < 31) {
            const int nb = (jt + 1) & 1;
            MBARRIER_EXPECT_TX(sb + SMB_ + 8 * nb, 16384 + 65536);
            BULK_G2S(sb + SK_ + nb * 16384, gk0 + (size_t)(jt + 1) * 16384,
                     16384, sb + SMB_ + 8 * nb);
            BULK_G2S(sb + SV_ + nb * 65536, gv0 + (size_t)(jt + 1) * 65536,
                     65536, sb + SMB_ + 8 * nb);
        }

        // ---- GEMM2: O += P @ V ----
        uint32_t Pa[8][4];
#pragma unroll
        for (int kc = 0; kc < 8; kc++) {
            int row = ib * 16 + (lane & 15);
            int cb  = kc * 16 + (lane >> 4) * 8;
            ldsm4(Pa[kc], sb + pbuf + row * 272 + cb * 2);
        }
        const uint32_t vbase = sb + SV_ + buf * 65536;
#pragma unroll
        for (int nf = 0; nf < 16; nf += 2) {
            uint32_t vb0[16], vb1[16];
            {
                int ch0 = half * 128 + nf * 8 + (lane & 7);
                int ch1 = ch0 + 8;
#pragma unroll
                for (int p = 0; p < 4; p++) {
                    int g = 4 * p + (lane >> 3);
                    ldsm4(vb0 + 4 * p, vbase + ch0 * 256 + ((g ^ (ch0 & 7)) << 4));
                    ldsm4(vb1 + 4 * p, vbase + ch1 * 256 + ((g ^ (ch1 & 7)) << 4));
                }
            }
#pragma unroll
            for (int kc = 0; kc < 8; kc++) {
                mma16816(accs[nf],     Pa[kc], vb0[2 * kc], vb0[2 * kc + 1]);
                mma16816(accs[nf + 1], Pa[kc], vb1[2 * kc], vb1[2 * kc + 1]);
            }
        }
    }

    lsA += __shfl_xor_sync(0xffffffffu, lsA, 1);
    lsA += __shfl_xor_sync(0xffffffffu, lsA, 2);
    lsB += __shfl_xor_sync(0xffffffffu, lsB, 1);
    lsB += __shfl_xor_sync(0xffffffffu, lsB, 2);
    if (tc == 0) {
        atomicAdd((float*)(smem + SL_ + (ib * 16 + gr) * 4), lsA);
        atomicAdd((float*)(smem + SL_ + (ib * 16 + gr + 8) * 4), lsB);
    }
    __syncthreads();

    const float gm = gamma[0];
    const int r0   = ib * 16 + gr;
    const float inv0 = 1.0f / *(float*)(smem + SL_ + r0 * 4);
    const float inv8 = 1.0f / *(float*)(smem + SL_ + (r0 + 8) * 4);
    const int i0 = qt * 64;
#pragma unroll
    for (int nf = 0; nf < 16; nf++) {
        int c = half * 128 + nf * 8 + tc * 2;
        size_t base0 = ((size_t)b * C_ + c) * N_ + i0;
        size_t base1 = base0 + N_;
        y[base0 + r0]     = gm * accs[nf][0] * inv0 + x[base0 + r0];
        y[base1 + r0]     = gm * accs[nf][1] * inv0 + x[base1 + r0];
        y[base0 + r0 + 8] = gm * accs[nf][2] * inv8 + x[base0 + r0 + 8];
        y[base1 + r0 + 8] = gm * accs[nf][3] * inv8 + x[base1 + r0 + 8];
    }
}

// ---------------------------------------------------------------------------
extern "C" void kernel_launch(void* const* d_in, const int* in_sizes, int n_in,
                              void* d_out, int out_size)
{
    const float* x     = (const float*)d_in[0];
    const float* wq    = (const float*)d_in[1];
    const float* bq    = (const float*)d_in[2];
    const float* wk    = (const float*)d_in[3];
    const float* bk    = (const float*)d_in[4];
    const float* wv    = (const float*)d_in[5];
    const float* bv    = (const float*)d_in[6];
    const float* gamma = (const float*)d_in[7];
    float* y = (float*)d_out;

    cudaFuncSetAttribute(xcvt_kernel,
                         cudaFuncAttributeMaxDynamicSharedMemorySize, XC_SMEM);
    cudaFuncSetAttribute(proj_all_kernel,
                         cudaFuncAttributeMaxDynamicSharedMemorySize, P_SMEM);
    cudaFuncSetAttribute(attn_kernel,
                         cudaFuncAttributeMaxDynamicSharedMemorySize, SMEM_TOTAL);

    xcvt_kernel    <<<dim3(4, 16, B_), 256, XC_SMEM>>>(x);
    proj_all_kernel<<<dim3(16, 5, B_), 512, P_SMEM>>>(x, wq, bq, wk, bk, wv, bv);
    attn_kernel    <<<dim3(64, B_), 256, SMEM_TOTAL>>>(x, gamma, y);
}

// round 7
// speedup vs baseline: 7.8495x; 1.0343x over previous
#include <cuda_runtime.h>
#include <cuda_bf16.h>
#include <stdint.h>

#define B_   8
#define C_   256
#define N_   4096
#define CQ_  32

// ---------------------------------------------------------------------------
// PTX helpers (sm_80/sm_90-class only -- NO tcgen05)
// ---------------------------------------------------------------------------
__device__ __forceinline__ uint32_t smem_u32(const void* p) {
    uint32_t a;
    asm("{ .reg .u64 t; cvta.to.shared.u64 t, %1; cvt.u32.u64 %0, t; }"
        : "=r"(a) : "l"(p));
    return a;
}

#define MBARRIER_INIT(mbar, count) \
    asm volatile("mbarrier.init.shared.b64 [%0], %1;" \
        :: "r"((uint32_t)(mbar)), "r"((uint32_t)(count)) : "memory")
#define MBARRIER_EXPECT_TX(mbar, bytes) \
    asm volatile("mbarrier.arrive.expect_tx.shared.b64 _, [%0], %1;" \
        :: "r"((uint32_t)(mbar)), "r"((uint32_t)(bytes)) : "memory")

#define MBARRIER_WAIT_PARITY(mbar, parity) do {                                   \
    uint32_t _m = (uint32_t)(mbar); uint32_t _p = (uint32_t)(parity);             \
    uint32_t _done;                                                               \
    asm volatile("{\n\t.reg .pred p;\n\t"                                         \
        "mbarrier.try_wait.parity.acquire.cta.shared::cta.b64 p, [%1], %2;\n\t"   \
        "selp.b32 %0, 1, 0, p;\n\t}"                                              \
        : "=r"(_done) : "r"(_m), "r"(_p) : "memory");                             \
    if (!_done) {                                                                 \
        asm volatile("{\n\t.reg .pred P1;\n\t"                                    \
            "WAIT_LOOP_%=:\n\t"                                                   \
            "mbarrier.try_wait.parity.acquire.cta.shared::cta.b64 P1, [%0], %1, 0x989680;\n\t" \
            "@P1 bra.uni WAIT_DONE_%=;\n\t"                                       \
            "bra.uni WAIT_LOOP_%=;\n\t"                                           \
            "WAIT_DONE_%=:\n\t}"                                                  \
            :: "r"(_m), "r"(_p) : "memory");                                      \
    }                                                                             \
} while (0)

#define BULK_G2S(dst, src, bytes, mbar) \
    asm volatile("cp.async.bulk.shared::cluster.global.mbarrier::complete_tx::bytes " \
        "[%0], [%1], %2, [%3];" \
        :: "r"((uint32_t)(dst)), "l"(__cvta_generic_to_global(src)), \
           "r"((uint32_t)(bytes)), "r"((uint32_t)(mbar)) : "memory")

__device__ __forceinline__ void ldsm4(uint32_t r[4], uint32_t addr) {
    asm volatile("ldmatrix.sync.aligned.m8n8.x4.shared.b16 {%0,%1,%2,%3}, [%4];"
        : "=r"(r[0]), "=r"(r[1]), "=r"(r[2]), "=r"(r[3]) : "r"(addr));
}

__device__ __forceinline__ void mma16816(float d[4], const uint32_t a[4],
                                         uint32_t b0, uint32_t b1) {
    asm volatile("mma.sync.aligned.m16n8k16.row.col.f32.bf16.bf16.f32 "
        "{%0,%1,%2,%3}, {%4,%5,%6,%7}, {%8,%9}, {%0,%1,%2,%3};"
        : "+f"(d[0]), "+f"(d[1]), "+f"(d[2]), "+f"(d[3])
        : "r"(a[0]), "r"(a[1]), "r"(a[2]), "r"(a[3]), "r"(b0), "r"(b1));
}

__device__ __forceinline__ uint32_t pack_bf16x2(float hi, float lo) {
    uint32_t r;
    asm("cvt.rn.satfinite.bf16x2.f32 %0, %1, %2;" : "=r"(r) : "f"(hi), "f"(lo));
    return r;
}

// ---------------------------------------------------------------------------
// Gmem scratch
// g_qh[b][qt64][64 rows][64 bf16: hi|lo]     8KB/tile
// g_kh[b][kt32][128 rows][64 bf16: hi|lo]    16KB/tile
// g_vh[b][kt32][256 ch][128 keys bf16]       64KB/tile
// g_xh/g_xl[b][nt16][kc4][n256][k64 bf16]    32KB/chunk, swizzled
// g_wc[mt5][kc4][hi 64x128B | lo 64x128B]    16KB/chunk, swizzled
// ---------------------------------------------------------------------------
__device__ __align__(16) unsigned char g_qh[(size_t)B_ * 64 * 8192];
__device__ __align__(16) unsigned char g_kh[(size_t)B_ * 32 * 16384];
__device__ __align__(16) unsigned char g_vh[(size_t)B_ * 32 * 65536];
__device__ __align__(16) unsigned char g_xh[(size_t)B_ * 16 * 4 * 32768];
__device__ __align__(16) unsigned char g_xl[(size_t)B_ * 16 * 4 * 32768];
__device__ __align__(16) unsigned char g_wc[(size_t)5 * 4 * 16384];

// ---------------------------------------------------------------------------
// wcvt: weights fp32 -> bf16 hi/lo pre-swizzled chunk tiles. grid (4,5), 256 thr
// ---------------------------------------------------------------------------
__global__ __launch_bounds__(256, 1)
void wcvt_kernel(const float* __restrict__ wq, const float* __restrict__ wk,
                 const float* __restrict__ wv)
{
    const int chunk = blockIdx.x;   // k chunk (64 cols)
    const int mt    = blockIdx.y;   // 0=qk, 1..4 = v row blocks
    const int tid   = threadIdx.x;
    unsigned char* base = g_wc + (size_t)(mt * 4 + chunk) * 16384;

#pragma unroll
    for (int it = 0; it < 2; it++) {
        int lin = tid + 256 * it;        // 0..511
        int row = lin >> 3;              // m 0..63
        int g   = lin & 7;               // k-group of 8
        int ck  = chunk * 64 + g * 8;
        const float* wp = (mt == 0)
            ? (row < 32 ? &wq[row * 256 + ck] : &wk[(row - 32) * 256 + ck])
            : &wv[(size_t)((mt - 1) * 64 + row) * 256 + ck];
        float4 v0 = *(const float4*)wp;
        float4 v1 = *(const float4*)(wp + 4);
        float fv[8] = {v0.x, v0.y, v0.z, v0.w, v1.x, v1.y, v1.z, v1.w};
        union { uint4 u; __nv_bfloat16 h[8]; } ph, pl;
#pragma unroll
        for (int j = 0; j < 8; j++) {
            ph.h[j] = __float2bfloat16(fv[j]);
            pl.h[j] = __float2bfloat16(fv[j] - __bfloat162float(ph.h[j]));
        }
        uint32_t off = row * 128 + ((g ^ (row & 7)) << 4);
        *(uint4*)(base + off)        = ph.u;
        *(uint4*)(base + 8192 + off) = pl.u;
    }
}

// ---------------------------------------------------------------------------
// xcvt: x fp32 [b][c][n] -> hi/lo bf16, transposed + swizzled chunk tiles.
// grid (4 kc, 16 nt, 8 b), 256 threads.
// ---------------------------------------------------------------------------
#define XC_STRIDE 72
#define XC_SMEM   (2 * 256 * XC_STRIDE * 2)

__global__ __launch_bounds__(256, 1)
void xcvt_kernel(const float* __restrict__ x)
{
    extern __shared__ __align__(16) unsigned char xsm[];
    __nv_bfloat16* smh = (__nv_bfloat16*)xsm;
    __nv_bfloat16* sml = smh + 256 * XC_STRIDE;

    const int kc = blockIdx.x;
    const int nt = blockIdx.y;
    const int b  = blockIdx.z;
    const int tid = threadIdx.x;
    const int c0g = kc * 64;
    const int n0g = nt * 256;

#pragma unroll
    for (int it = 0; it < 4; it++) {
        int lin = tid + 256 * it;
        int c4  = lin >> 6;
        int f4  = lin & 63;
        int c0  = c4 * 4;
        float4 v[4];
#pragma unroll
        for (int r = 0; r < 4; r++)
            v[r] = *(const float4*)&x[((size_t)b * C_ + c0g + c0 + r) * N_ + n0g + f4 * 4];
#pragma unroll
        for (int nn = 0; nn < 4; nn++) {
            int n = f4 * 4 + nn;
            float fv[4] = {nn == 0 ? v[0].x : nn == 1 ? v[0].y : nn == 2 ? v[0].z : v[0].w,
                           nn == 0 ? v[1].x : nn == 1 ? v[1].y : nn == 2 ? v[1].z : v[1].w,
                           nn == 0 ? v[2].x : nn == 1 ? v[2].y : nn == 2 ? v[2].z : v[2].w,
                           nn == 0 ? v[3].x : nn == 1 ? v[3].y : nn == 2 ? v[3].z : v[3].w};
            __nv_bfloat16 h[4], l[4];
#pragma unroll
            for (int r = 0; r < 4; r++) {
                h[r] = __float2bfloat16(fv[r]);
                l[r] = __float2bfloat16(fv[r] - __bfloat162float(h[r]));
            }
            *(uint2*)&smh[n * XC_STRIDE + c0] = *(uint2*)h;
            *(uint2*)&sml[n * XC_STRIDE + c0] = *(uint2*)l;
        }
    }
    __syncthreads();

    const size_t base = (((size_t)b * 16 + nt) * 4 + kc) * 32768;
#pragma unroll
    for (int it = 0; it < 8; it++) {
        int id = tid + 256 * it;
        int n  = id >> 3;
        int g  = id & 7;
        uint32_t off = n * 128 + ((g ^ (n & 7)) << 4);
        *(uint4*)(g_xh + base + off) = *(uint4*)&smh[n * XC_STRIDE + g * 8];
        *(uint4*)(g_xl + base + off) = *(uint4*)&sml[n * XC_STRIDE + g * 8];
    }
}

// ---------------------------------------------------------------------------
// proj_all: q/k/v = W @ x + b via mma.sync (hi/lo 3-term split).
// grid (32 nt, 5 mt, 8 b), 256 threads (8 warps: 4 m16 x 2 n64), 2 CTAs/SM.
// n-tile = 128 columns. W chunk-staged via bulk copy (pre-converted g_wc).
// ---------------------------------------------------------------------------
#define PW_OFF   0u         // 2 x 16KB W chunk (hi 8KB | lo 8KB)
#define PX_OFF   32768u     // 2 x (16KB hi + 16KB lo)
#define PB_OFF   98304u     // bias 64 floats
#define PMB_OFF  98560u     // 2 mbarriers
#define P_SMEM   98592

__global__ __launch_bounds__(256, 2)
void proj_all_kernel(const float* __restrict__ bq, const float* __restrict__ bk,
                     const float* __restrict__ bv)
{
    extern __shared__ __align__(1024) unsigned char psm[];
    const uint32_t sb = smem_u32(psm);
    const uint32_t mb0 = sb + PMB_OFF;
    const uint32_t mb1 = mb0 + 8;

    const int tid  = threadIdx.x;
    const int lane = tid & 31;
    const int w    = tid >> 5;
    const int nt   = blockIdx.x;     // 0..31, n0 = nt*128
    const int mt   = blockIdx.y;
    const int b    = blockIdx.z;
    const int gr   = lane >> 2;
    const int tc   = lane & 3;

    float* sBias = (float*)(psm + PB_OFF);

    if (tid == 0) { MBARRIER_INIT(mb0, 1); MBARRIER_INIT(mb1, 1); }
    if (tid < 64) {
        sBias[tid] = (mt == 0) ? (tid < 32 ? bq[tid] : bk[tid - 32])
                               : bv[(mt - 1) * 64 + tid];
    }
    __syncthreads();

    const int xnt  = nt >> 1;
    const size_t xoff = (size_t)(nt & 1) * 16384;   // n-half within n256 tile
    const size_t xbase = ((size_t)b * 16 + xnt) * 4 * 32768;
    const unsigned char* wbase = g_wc + (size_t)mt * 4 * 16384;

    if (tid == 0) {
        MBARRIER_EXPECT_TX(mb0, 49152);
        BULK_G2S(sb + PW_OFF, wbase, 16384, mb0);
        BULK_G2S(sb + PX_OFF,         g_xh + xbase + xoff, 16384, mb0);
        BULK_G2S(sb + PX_OFF + 16384, g_xl + xbase + xoff, 16384, mb0);
    }

    float acc[8][4];
#pragma unroll
    for (int i = 0; i < 8; i++)
#pragma unroll
        for (int j = 0; j < 4; j++) acc[i][j] = 0.f;

    const int mrow = (w >> 1) * 16;     // m block (0..3)
    const int nwp  = (w & 1) * 64;      // n half (0..1)

    for (int c = 0; c < 4; c++) {
        if (c > 0) __syncthreads();
        if (tid == 0 && c < 3) {
            const uint32_t nmb = ((c + 1) & 1) ? mb1 : mb0;
            const uint32_t nb  = ((c + 1) & 1);
            MBARRIER_EXPECT_TX(nmb, 49152);
            BULK_G2S(sb + PW_OFF + nb * 16384, wbase + (size_t)(c + 1) * 16384,
                     16384, nmb);
            BULK_G2S(sb + PX_OFF + nb * 32768,
                     g_xh + xbase + (size_t)(c + 1) * 32768 + xoff, 16384, nmb);
            BULK_G2S(sb + PX_OFF + nb * 32768 + 16384,
                     g_xl + xbase + (size_t)(c + 1) * 32768 + xoff, 16384, nmb);
        }
        MBARRIER_WAIT_PARITY((c & 1) ? mb1 : mb0, (c >> 1) & 1);

        // A fragments from W chunk buffer
        uint32_t Ahi[4][4], Alo[4][4];
        {
            int row = mrow + (lane & 15);
            int sw  = row & 7;
            uint32_t rb = sb + PW_OFF + (c & 1) * 16384 + row * 128;
#pragma unroll
            for (int k16 = 0; k16 < 4; k16++) {
                int g = 2 * k16 + (lane >> 4);
                ldsm4(Ahi[k16], rb + ((g ^ sw) << 4));
                ldsm4(Alo[k16], rb + 8192 + ((g ^ sw) << 4));
            }
        }

        const uint32_t xh = sb + PX_OFF + (c & 1) * 32768;
        const uint32_t xl = xh + 16384;
#pragma unroll
        for (int nb = 0; nb < 8; nb++) {
            uint32_t Bh[8], Bl[8];
            int row = nwp + nb * 8 + (lane & 7);
            int sw  = row & 7;
            int ga  = lane >> 3;
            ldsm4(Bh,     xh + row * 128 + ((ga ^ sw) << 4));
            ldsm4(Bh + 4, xh + row * 128 + (((4 + ga) ^ sw) << 4));
            ldsm4(Bl,     xl + row * 128 + ((ga ^ sw) << 4));
            ldsm4(Bl + 4, xl + row * 128 + (((4 + ga) ^ sw) << 4));
#pragma unroll
            for (int k16 = 0; k16 < 4; k16++) {
                mma16816(acc[nb], Ahi[k16], Bh[2 * k16], Bh[2 * k16 + 1]);
                mma16816(acc[nb], Ahi[k16], Bl[2 * k16], Bl[2 * k16 + 1]);
                mma16816(acc[nb], Alo[k16], Bh[2 * k16], Bh[2 * k16 + 1]);
            }
        }
    }
    __syncthreads();

    // stage accum to smem [64 m][132 n stride] fp32 (reuse X region)
    float* st = (float*)(psm + PX_OFF);
#pragma unroll
    for (int nb = 0; nb < 8; nb++) {
        int ncol = nwp + nb * 8 + tc * 2;
        *(float2*)&st[(mrow + gr) * 132 + ncol]     = make_float2(acc[nb][0], acc[nb][1]);
        *(float2*)&st[(mrow + gr + 8) * 132 + ncol] = make_float2(acc[nb][2], acc[nb][3]);
    }
    __syncthreads();

    if (mt == 0) {
        // q rows 0..31 -> g_qh (64-row tiles), k rows 32..63 -> g_kh (128-row)
#pragma unroll
        for (int it = 0; it < 8; it++) {
            int id    = tid + 256 * it;      // 0..2047
            int which = id >> 10;            // 0=q, 1=k
            int m2    = id & 1023;
            int nrow  = m2 >> 3;             // 0..127
            int g     = m2 & 7;
            int o0    = (g & 3) * 8;
            bool islo = g >= 4;
            union { uint4 u; __nv_bfloat16 h[8]; } pk;
#pragma unroll
            for (int j = 0; j < 8; j++) {
                float v = st[(which * 32 + o0 + j) * 132 + nrow]
                        + sBias[which * 32 + o0 + j];
                __nv_bfloat16 hi = __float2bfloat16(v);
                pk.h[j] = islo ? __float2bfloat16(v - __bfloat162float(hi)) : hi;
            }
            unsigned char* dst;
            if (which) {
                dst = g_kh + ((size_t)(b * 32 + nt)) * 16384
                    + nrow * 128 + ((g ^ (nrow & 7)) << 4);
            } else {
                int tile = nt * 2 + (nrow >> 6);
                int r    = nrow & 63;
                dst = g_qh + ((size_t)(b * 64 + tile)) * 8192
                    + r * 128 + ((g ^ (r & 7)) << 4);
            }
            *(uint4*)dst = pk.u;
        }
    } else {
        const int ch0 = (mt - 1) * 64;
#pragma unroll
        for (int it = 0; it < 4; it++) {
            int id  = tid + 256 * it;        // 0..1023
            int chl = id >> 4;               // 0..63
            int kg  = id & 15;               // key group of 8 (0..15)
            int chg = ch0 + chl;
            float bb = sBias[chl];
            union { uint4 u; __nv_bfloat16 h[8]; } pk;
#pragma unroll
            for (int j = 0; j < 8; j++)
                pk.h[j] = __float2bfloat16(st[chl * 132 + kg * 8 + j] + bb);
            *(uint4*)(g_vh + ((size_t)(b * 32 + nt)) * 65536
                      + chg * 256 + ((kg ^ (chg & 7)) << 4)) = pk.u;
        }
    }
}

// ---------------------------------------------------------------------------
// Attention: mma.sync flash attention, 64 queries/CTA, grid (64, 8), 256 thr
// (unchanged from round 6)
// ---------------------------------------------------------------------------
#define SQ_  0u
#define SK_  8192u
#define SV_  40960u
#define SP0_ 172032u
#define SP1_ 189440u
#define SL_  206848u
#define SMB_ 207104u
#define SMEM_TOTAL 207136

__global__ __launch_bounds__(256, 1)
void attn_kernel(const float* __restrict__ x,
                 const float* __restrict__ gamma,
                 float* __restrict__ y)
{
    extern __shared__ __align__(16) unsigned char smem[];
    const uint32_t sb = smem_u32(smem);
    const int tid  = threadIdx.x;
    const int lane = tid & 31;
    const int w    = tid >> 5;
    const int b    = blockIdx.y;
    const int qt   = blockIdx.x;
    const int ib   = w >> 1;
    const int half = w & 1;
    const int gr   = lane >> 2;
    const int tc   = lane & 3;

    if (tid < 64) *(float*)(smem + SL_ + tid * 4) = 0.f;
    if (tid == 0) {
        MBARRIER_INIT(sb + SMB_ + 0, 1);
        MBARRIER_INIT(sb + SMB_ + 8, 1);
    }
    __syncthreads();

    const unsigned char* gq  = g_qh + ((size_t)(b * 64 + qt)) * 8192;
    const unsigned char* gk0 = g_kh + ((size_t)b * 32) * 16384;
    const unsigned char* gv0 = g_vh + ((size_t)b * 32) * 65536;

    if (tid == 0) {
        MBARRIER_EXPECT_TX(sb + SMB_ + 0, 8192 + 16384 + 65536);
        BULK_G2S(sb + SQ_, gq, 8192, sb + SMB_ + 0);
        BULK_G2S(sb + SK_, gk0, 16384, sb + SMB_ + 0);
        BULK_G2S(sb + SV_, gv0, 65536, sb + SMB_ + 0);
        MBARRIER_EXPECT_TX(sb + SMB_ + 8, 16384 + 65536);
        BULK_G2S(sb + SK_ + 16384, gk0 + 16384, 16384, sb + SMB_ + 8);
        BULK_G2S(sb + SV_ + 65536, gv0 + 65536, 65536, sb + SMB_ + 8);
    }

    float accs[16][4];
#pragma unroll
    for (int i = 0; i < 16; i++)
#pragma unroll
        for (int j = 0; j < 4; j++) accs[i][j] = 0.f;

    uint32_t Qa[4][4];
    float lsA = 0.f, lsB = 0.f;

    for (int jt = 0; jt < 32; jt++) {
        const int buf = jt & 1;
        const uint32_t pbuf = buf ? SP1_ : SP0_;

        MBARRIER_WAIT_PARITY(sb + SMB_ + 8 * buf, (jt >> 1) & 1);

        if (jt == 0) {
#pragma unroll
            for (int c = 0; c < 4; c++) {
                int row = ib * 16 + (lane & 15);
                int g   = 2 * c + (lane >> 4);
                ldsm4(Qa[c], sb + SQ_ + row * 128 + ((g ^ (row & 7)) << 4));
            }
        }

        const uint32_t kbase = sb + SK_ + buf * 16384;
#pragma unroll
        for (int nf = 0; nf < 8; nf += 2) {
            uint32_t kb0[8], kb1[8];
            {
                int j0 = half * 64 + nf * 8 + (lane & 7);
                int j1 = j0 + 8;
                int ga = (lane >> 3), gb = 4 + (lane >> 3);
                ldsm4(kb0,     kbase + j0 * 128 + ((ga ^ (j0 & 7)) << 4));
                ldsm4(kb0 + 4, kbase + j0 * 128 + ((gb ^ (j0 & 7)) << 4));
                ldsm4(kb1,     kbase + j1 * 128 + ((ga ^ (j1 & 7)) << 4));
                ldsm4(kb1 + 4, kbase + j1 * 128 + ((gb ^ (j1 & 7)) << 4));
            }
            float d0[4] = {0.f, 0.f, 0.f, 0.f};
            float d1[4] = {0.f, 0.f, 0.f, 0.f};
#pragma unroll
            for (int c = 0; c < 4; c++) {
                if (c < 2) {
                    mma16816(d0, Qa[c], kb0[2 * c], kb0[2 * c + 1]);
                    mma16816(d1, Qa[c], kb1[2 * c], kb1[2 * c + 1]);
                }
                mma16816(d0, Qa[c], kb0[(2 * c + 4) & 7], kb0[(2 * c + 5) & 7]);
                mma16816(d1, Qa[c], kb1[(2 * c + 4) & 7], kb1[(2 * c + 5) & 7]);
            }
#pragma unroll
            for (int q2 = 0; q2 < 2; q2++) {
                float* d = q2 ? d1 : d0;
                float e0 = __expf(d[0]), e1 = __expf(d[1]);
                float e2 = __expf(d[2]), e3 = __expf(d[3]);
                lsA += e0 + e1;
                lsB += e2 + e3;
                int colb = (half * 64 + (nf + q2) * 8 + tc * 2) * 2;
                int r0   = ib * 16 + gr;
                *(uint32_t*)(smem + pbuf + r0 * 272 + colb)       = pack_bf16x2(e1, e0);
                *(uint32_t*)(smem + pbuf + (r0 + 8) * 272 + colb) = pack_bf16x2(e3, e2);
            }
        }
        __syncthreads();

        if (tid == 0 && jt >= 1 && jt < 31) {
            const int nb = (jt + 1) & 1;
            MBARRIER_EXPECT_TX(sb + SMB_ + 8 * nb, 16384 + 65536);
            BULK_G2S(sb + SK_ + nb * 16384, gk0 + (size_t)(jt + 1) * 16384,
                     16384, sb + SMB_ + 8 * nb);
            BULK_G2S(sb + SV_ + nb * 65536, gv0 + (size_t)(jt + 1) * 65536,
                     65536, sb + SMB_ + 8 * nb);
        }

        uint32_t Pa[8][4];
#pragma unroll
        for (int kc = 0; kc < 8; kc++) {
            int row = ib * 16 + (lane & 15);
            int cb  = kc * 16 + (lane >> 4) * 8;
            ldsm4(Pa[kc], sb + pbuf + row * 272 + cb * 2);
        }
        const uint32_t vbase = sb + SV_ + buf * 65536;
#pragma unroll
        for (int nf = 0; nf < 16; nf += 2) {
            uint32_t vb0[16], vb1[16];
            {
                int ch0 = half * 128 + nf * 8 + (lane & 7);
                int ch1 = ch0 + 8;
#pragma unroll
                for (int p = 0; p < 4; p++) {
                    int g = 4 * p + (lane >> 3);
                    ldsm4(vb0 + 4 * p, vbase + ch0 * 256 + ((g ^ (ch0 & 7)) << 4));
                    ldsm4(vb1 + 4 * p, vbase + ch1 * 256 + ((g ^ (ch1 & 7)) << 4));
                }
            }
#pragma unroll
            for (int kc = 0; kc < 8; kc++) {
                mma16816(accs[nf],     Pa[kc], vb0[2 * kc], vb0[2 * kc + 1]);
                mma16816(accs[nf + 1], Pa[kc], vb1[2 * kc], vb1[2 * kc + 1]);
            }
        }
    }

    lsA += __shfl_xor_sync(0xffffffffu, lsA, 1);
    lsA += __shfl_xor_sync(0xffffffffu, lsA, 2);
    lsB += __shfl_xor_sync(0xffffffffu, lsB, 1);
    lsB += __shfl_xor_sync(0xffffffffu, lsB, 2);
    if (tc == 0) {
        atomicAdd((float*)(smem + SL_ + (ib * 16 + gr) * 4), lsA);
        atomicAdd((float*)(smem + SL_ + (ib * 16 + gr + 8) * 4), lsB);
    }
    __syncthreads();

    const float gm = gamma[0];
    const int r0   = ib * 16 + gr;
    const float inv0 = 1.0f / *(float*)(smem + SL_ + r0 * 4);
    const float inv8 = 1.0f / *(float*)(smem + SL_ + (r0 + 8) * 4);
    const int i0 = qt * 64;
#pragma unroll
    for (int nf = 0; nf < 16; nf++) {
        int c = half * 128 + nf * 8 + tc * 2;
        size_t base0 = ((size_t)b * C_ + c) * N_ + i0;
        size_t base1 = base0 + N_;
        y[base0 + r0]     = gm * accs[nf][0] * inv0 + x[base0 + r0];
        y[base1 + r0]     = gm * accs[nf][1] * inv0 + x[base1 + r0];
        y[base0 + r0 + 8] = gm * accs[nf][2] * inv8 + x[base0 + r0 + 8];
        y[base1 + r0 + 8] = gm * accs[nf][3] * inv8 + x[base1 + r0 + 8];
    }
}

// ---------------------------------------------------------------------------
extern "C" void kernel_launch(void* const* d_in, const int* in_sizes, int n_in,
                              void* d_out, int out_size)
{
    const float* x     = (const float*)d_in[0];
    const float* wq    = (const float*)d_in[1];
    const float* bq    = (const float*)d_in[2];
    const float* wk    = (const float*)d_in[3];
    const float* bk    = (const float*)d_in[4];
    const float* wv    = (const float*)d_in[5];
    const float* bv    = (const float*)d_in[6];
    const float* gamma = (const float*)d_in[7];
    float* y = (float*)d_out;

    cudaFuncSetAttribute(xcvt_kernel,
                         cudaFuncAttributeMaxDynamicSharedMemorySize, XC_SMEM);
    cudaFuncSetAttribute(proj_all_kernel,
                         cudaFuncAttributeMaxDynamicSharedMemorySize, P_SMEM);
    cudaFuncSetAttribute(attn_kernel,
                         cudaFuncAttributeMaxDynamicSharedMemorySize, SMEM_TOTAL);

    wcvt_kernel    <<<dim3(4, 5, 1), 256>>>(wq, wk, wv);
    xcvt_kernel    <<<dim3(4, 16, B_), 256, XC_SMEM>>>(x);
    proj_all_kernel<<<dim3(32, 5, B_), 256, P_SMEM>>>(bq, bk, bv);
    attn_kernel    <<<dim3(64, B_), 256, SMEM_TOTAL>>>(x, gamma, y);
}